// round 6
// baseline (speedup 1.0000x reference)
#include <cuda_runtime.h>

#define NN 20000
#define EE 320000
#define ET (EE + NN)
#define BB 128

typedef unsigned long long ull;

__device__ __forceinline__ ull pk2(float lo, float hi) {
    ull r; asm("mov.b64 %0, {%1, %2};" : "=l"(r) : "f"(lo), "f"(hi)); return r;
}
__device__ __forceinline__ void upk2(ull v, float& lo, float& hi) {
    asm("mov.b64 {%0, %1}, %2;" : "=f"(lo), "=f"(hi) : "l"(v));
}
__device__ __forceinline__ void fma2(ull& d, ull a, ull b) {
    asm("fma.rn.f32x2 %0, %1, %2, %0;" : "+l"(d) : "l"(a), "l"(b));
}

// ---------------- scratch (device globals; no runtime allocation) ----------
__device__ int   g_flag;
__device__ int   g_src[EE], g_dst[EE], g_batch[NN];
__device__ int   g_deg[NN], g_cur[NN], g_off[NN + 1];
__device__ int   g_csr[ET];
__device__ float g_h0[NN * 64];
__device__ float g_pre[(size_t)NN * 512];      // aggpre [N][h*64+k]
__device__ float g_as[NN * 8], g_ad[NN * 8];
__device__ float g_Vs[64 * 8], g_Vd[64 * 8];
__device__ float g_outf[NN * 64];
__device__ float g_e2[NN];
__device__ float g_hs[BB * 64], g_cs[BB * 64], g_qstar[BB * 128];
__device__ int   g_seg[BB + 1];

// ---------------- dtype detection (int64 vs int32 index buffers) -----------
__global__ void k_detect(const int* buf) {
    int t = threadIdx.x;
    int any = 0;
    for (int i = 2 * t + 1; i < 2048; i += 2 * 256) any |= (buf[i] != 0);
    __shared__ int s;
    if (t == 0) s = 0;
    __syncthreads();
    if (any) atomicOr(&s, 1);
    __syncthreads();
    if (t == 0) g_flag = s ? 0 : 1;  // 1 => int64
}

// ---------------- zero/seed-init per launch ---------------------------------
__global__ void k_init(int n) {
    int tot = 2 * n + BB * 128 + 2 * BB * 64;
    for (int i = blockIdx.x * blockDim.x + threadIdx.x; i < tot;
         i += gridDim.x * blockDim.x) {
        if (i < n) g_deg[i] = 1;            // self-loop pre-counted
        else if (i < 2 * n) g_cur[i - n] = 0;
        else {
            int j = i - 2 * n;
            if (j < BB * 128) g_qstar[j] = 0.f;
            else {
                j -= BB * 128;
                if (j < BB * 64) g_hs[j] = 0.f;
                else g_cs[j - BB * 64] = 0.f;
            }
        }
    }
}

// ---------------- convert indices + count degrees ---------------------------
__global__ void k_convert(const void* edge, const void* batch, int E, int n) {
    int is64 = g_flag;
    for (int i = blockIdx.x * blockDim.x + threadIdx.x; i < E;
         i += gridDim.x * blockDim.x) {
        int s, d;
        if (is64) {
            const long long* p = (const long long*)edge;
            s = (int)p[i];
            d = (int)p[(size_t)E + i];
        } else {
            const int* p = (const int*)edge;
            s = p[i];
            d = p[E + i];
        }
        g_src[i] = s;
        g_dst[i] = d;
        atomicAdd(&g_deg[d], 1);
        if (i < n) {
            g_batch[i] = is64 ? (int)((const long long*)batch)[i]
                              : ((const int*)batch)[i];
        }
    }
}

// ---------------- exclusive scan + segment starts (single block) ------------
__global__ void k_scanseg(int n) {
    __shared__ int warp_sums[32];
    __shared__ int carry_s;
    int t = threadIdx.x, lane = t & 31, wid = t >> 5;
    // segment starts for sorted batch (no barriers used here)
    if (t <= BB) {
        if (t == BB) g_seg[BB] = n;
        else {
            int lo = 0, hi = n;
            while (lo < hi) {
                int mid = (lo + hi) >> 1;
                if (g_batch[mid] < t) lo = mid + 1;
                else hi = mid;
            }
            g_seg[t] = lo;
        }
    }
    if (t == 0) carry_s = 0;
    __syncthreads();
    for (int base = 0; base < n; base += 1024) {
        int v = (base + t < n) ? g_deg[base + t] : 0;
        int xv = v;
#pragma unroll
        for (int o = 1; o < 32; o <<= 1) {
            int y = __shfl_up_sync(0xffffffffu, xv, o);
            if (lane >= o) xv += y;
        }
        if (lane == 31) warp_sums[wid] = xv;
        __syncthreads();
        if (wid == 0) {
            int s = warp_sums[lane];
#pragma unroll
            for (int o = 1; o < 32; o <<= 1) {
                int y = __shfl_up_sync(0xffffffffu, s, o);
                if (lane >= o) s += y;
            }
            warp_sums[lane] = s;
        }
        __syncthreads();
        int c0 = carry_s;
        int pre = c0 + (wid ? warp_sums[wid - 1] : 0);
        if (base + t < n) g_off[base + t] = pre + xv - v;
        int tot = warp_sums[31];
        __syncthreads();
        if (t == 0) carry_s = c0 + tot;
    }
    __syncthreads();
    if (t == 0) g_off[n] = carry_s;
}

// ---------------- Vs[k][h] = sum_c Wg[k, h*64+c] att_src[h,c] ---------------
__global__ void k_prevec(const float* __restrict__ Wg,
                         const float* __restrict__ att_src,
                         const float* __restrict__ att_dst) {
    int k = blockIdx.x, c = threadIdx.x;
    int lane = c & 31, w = c >> 5;
    __shared__ float sS[2][8], sD[2][8];
    float ps[8], pd[8];
#pragma unroll
    for (int h = 0; h < 8; h++) {
        float wv = Wg[k * 512 + h * 64 + c];
        ps[h] = wv * att_src[h * 64 + c];
        pd[h] = wv * att_dst[h * 64 + c];
    }
#pragma unroll
    for (int h = 0; h < 8; h++) {
        for (int o = 16; o; o >>= 1) {
            ps[h] += __shfl_xor_sync(0xffffffffu, ps[h], o);
            pd[h] += __shfl_xor_sync(0xffffffffu, pd[h], o);
        }
    }
    if (lane == 0) {
#pragma unroll
        for (int h = 0; h < 8; h++) { sS[w][h] = ps[h]; sD[w][h] = pd[h]; }
    }
    __syncthreads();
    if (c < 8) g_Vs[k * 8 + c] = sS[0][c] + sS[1][c];
    else if (c < 16) g_Vd[k * 8 + (c - 8)] = sD[0][c - 8] + sD[1][c - 8];
}

// ---------------- h0 = relu(x @ W0 + b0); a_s/a_d = h0 @ [Vs|Vd] ------------
__global__ void k_h0attn(const float* __restrict__ x,
                         const float* __restrict__ W0,
                         const float* __restrict__ b0, int n) {
    __shared__ float Ws[25 * 64];
    __shared__ float xs[16][26];
    __shared__ float Vsm[64][17];
    __shared__ float h0s[16][65];
    int t = threadIdx.x;  // 256
    int n0 = blockIdx.x * 16;
    for (int idx = t; idx < 1600; idx += 256) Ws[idx] = W0[idx];
    for (int idx = t; idx < 400; idx += 256) {
        int r = idx / 25, k = idx % 25;
        int gr = n0 + r;
        xs[r][k] = (gr < n) ? x[gr * 25 + k] : 0.f;
    }
    for (int idx = t; idx < 1024; idx += 256) {
        int k = idx >> 4, o = idx & 15;
        Vsm[k][o] = (o < 8) ? g_Vs[k * 8 + o] : g_Vd[k * 8 + (o - 8)];
    }
    __syncthreads();
    int j = t & 63, rb = t >> 6;
#pragma unroll
    for (int i = 0; i < 4; i++) {
        int r = rb * 4 + i;
        float acc = b0[j];
#pragma unroll
        for (int k = 0; k < 25; k++) acc += xs[r][k] * Ws[k * 64 + j];
        float v = fmaxf(acc, 0.f);
        h0s[r][j] = v;
        int gr = n0 + r;
        if (gr < n) g_h0[gr * 64 + j] = v;
    }
    __syncthreads();
    int row = t >> 4, o = t & 15;
    float acc = 0.f;
#pragma unroll 16
    for (int k = 0; k < 64; k++) acc += h0s[row][k] * Vsm[k][o];
    int gr = n0 + row;
    if (gr < n) {
        if (o < 8) g_as[gr * 8 + o] = acc;
        else       g_ad[gr * 8 + (o - 8)] = acc;
    }
}

__global__ void k_scatter(int E, int n) {
    int tot = E + n;
    for (int i = blockIdx.x * blockDim.x + threadIdx.x; i < tot;
         i += gridDim.x * blockDim.x) {
        int d = (i < E) ? g_dst[i] : (i - E);
        int s = (i < E) ? g_src[i] : (i - E);
        int pos = g_off[d] + atomicAdd(&g_cur[d], 1);
        g_csr[pos] = s;
    }
}

// ---------------- warp-per-dst softmax + aggregate in h0-space --------------
__global__ void k_agg(int n) {
    int gw = (blockIdx.x * blockDim.x + threadIdx.x) >> 5;
    int lane = threadIdx.x & 31;
    if (gw >= n) return;
    int start = g_off[gw], end = g_off[gw + 1];
    float4 adA = *(const float4*)(g_ad + gw * 8);
    float4 adB = *(const float4*)(g_ad + gw * 8 + 4);
    float ad0 = adA.x, ad1 = adA.y, ad2 = adA.z, ad3 = adA.w;
    float ad4 = adB.x, ad5 = adB.y, ad6 = adB.z, ad7 = adB.w;

    float lm[8];
#pragma unroll
    for (int h = 0; h < 8; h++) lm[h] = -1e30f;
    for (int j = start + lane; j < end; j += 32) {
        int s = g_csr[j];
        float4 aA = *(const float4*)(g_as + s * 8);
        float4 aB = *(const float4*)(g_as + s * 8 + 4);
        float e;
        e = aA.x + ad0; e = (e > 0.f) ? e : 0.2f * e; lm[0] = fmaxf(lm[0], e);
        e = aA.y + ad1; e = (e > 0.f) ? e : 0.2f * e; lm[1] = fmaxf(lm[1], e);
        e = aA.z + ad2; e = (e > 0.f) ? e : 0.2f * e; lm[2] = fmaxf(lm[2], e);
        e = aA.w + ad3; e = (e > 0.f) ? e : 0.2f * e; lm[3] = fmaxf(lm[3], e);
        e = aB.x + ad4; e = (e > 0.f) ? e : 0.2f * e; lm[4] = fmaxf(lm[4], e);
        e = aB.y + ad5; e = (e > 0.f) ? e : 0.2f * e; lm[5] = fmaxf(lm[5], e);
        e = aB.z + ad6; e = (e > 0.f) ? e : 0.2f * e; lm[6] = fmaxf(lm[6], e);
        e = aB.w + ad7; e = (e > 0.f) ? e : 0.2f * e; lm[7] = fmaxf(lm[7], e);
    }
#pragma unroll
    for (int h = 0; h < 8; h++)
        for (int o = 16; o; o >>= 1)
            lm[h] = fmaxf(lm[h], __shfl_xor_sync(0xffffffffu, lm[h], o));
    float ls[8];
#pragma unroll
    for (int h = 0; h < 8; h++) ls[h] = 0.f;
    for (int j = start + lane; j < end; j += 32) {
        int s = g_csr[j];
        float4 aA = *(const float4*)(g_as + s * 8);
        float4 aB = *(const float4*)(g_as + s * 8 + 4);
        float e;
        e = aA.x + ad0; e = (e > 0.f) ? e : 0.2f * e; ls[0] += __expf(e - lm[0]);
        e = aA.y + ad1; e = (e > 0.f) ? e : 0.2f * e; ls[1] += __expf(e - lm[1]);
        e = aA.z + ad2; e = (e > 0.f) ? e : 0.2f * e; ls[2] += __expf(e - lm[2]);
        e = aA.w + ad3; e = (e > 0.f) ? e : 0.2f * e; ls[3] += __expf(e - lm[3]);
        e = aB.x + ad4; e = (e > 0.f) ? e : 0.2f * e; ls[4] += __expf(e - lm[4]);
        e = aB.y + ad5; e = (e > 0.f) ? e : 0.2f * e; ls[5] += __expf(e - lm[5]);
        e = aB.z + ad6; e = (e > 0.f) ? e : 0.2f * e; ls[6] += __expf(e - lm[6]);
        e = aB.w + ad7; e = (e > 0.f) ? e : 0.2f * e; ls[7] += __expf(e - lm[7]);
    }
#pragma unroll
    for (int h = 0; h < 8; h++)
        for (int o = 16; o; o >>= 1)
            ls[h] += __shfl_xor_sync(0xffffffffu, ls[h], o);
    float inv[8];
#pragma unroll
    for (int h = 0; h < 8; h++) inv[h] = 1.f / ls[h];

    float advl = (lane == 0) ? ad0 : (lane == 1) ? ad1 : (lane == 2) ? ad2 :
                 (lane == 3) ? ad3 : (lane == 4) ? ad4 : (lane == 5) ? ad5 :
                 (lane == 6) ? ad6 : ad7;
    float lml  = (lane == 0) ? lm[0] : (lane == 1) ? lm[1] : (lane == 2) ? lm[2] :
                 (lane == 3) ? lm[3] : (lane == 4) ? lm[4] : (lane == 5) ? lm[5] :
                 (lane == 6) ? lm[6] : lm[7];
    float invl = (lane == 0) ? inv[0] : (lane == 1) ? inv[1] : (lane == 2) ? inv[2] :
                 (lane == 3) ? inv[3] : (lane == 4) ? inv[4] : (lane == 5) ? inv[5] :
                 (lane == 6) ? inv[6] : inv[7];

    // pass 3: one edge at a time, packed f32x2 accumulate
    ull acc2[8];
#pragma unroll
    for (int h = 0; h < 8; h++) acc2[h] = 0ULL;
    for (int j = start; j < end; j++) {
        int s = g_csr[j];
        float alv = 0.f;
        if (lane < 8) {
            float a = g_as[s * 8 + lane];
            float e = a + advl;
            e = (e > 0.f) ? e : 0.2f * e;
            alv = __expf(e - lml) * invl;
        }
        ull v = *(const ull*)(g_h0 + (size_t)s * 64 + lane * 2);
#pragma unroll
        for (int h = 0; h < 8; h++) {
            float a = __shfl_sync(0xffffffffu, alv, h);
            fma2(acc2[h], pk2(a, a), v);
        }
    }
#pragma unroll
    for (int h = 0; h < 8; h++)
        *(ull*)(g_pre + (size_t)gw * 512 + h * 64 + lane * 2) = acc2[h];
}

// ---------------- fused: out = relu(relu(pre (x)_h Wg_h + bg) @ Wh + bh) ----
// 128 threads; per-thread tile 8(rows, as 4 f32x2 pairs) x 4(cols); FFMA2.
__global__ void k_fused(const float* __restrict__ Wg,
                        const float* __restrict__ bg,
                        const float* __restrict__ Wh,
                        const float* __restrict__ bh, int n) {
    __shared__ float Pb[64][68];   // P_h: [k][row]
    __shared__ float Wgb[64][68];  // Wg_h: [k][c]
    __shared__ float Whb[64][68];  // Wh_h: [c][c2]
    __shared__ float Tb[64][68];   // T_h: [c][row]
    int row0 = blockIdx.x * 64;
    int t = threadIdx.x;  // 128
    int tx = t & 15, ty = t >> 4;  // tx: col group (4 cols), ty: row group (8 rows)
    ull acc[4][4];
#pragma unroll
    for (int i = 0; i < 4; i++)
#pragma unroll
        for (int j = 0; j < 4; j++) acc[i][j] = 0ULL;

    for (int h = 0; h < 8; h++) {
        __syncthreads();
        for (int idx = t; idx < 4096; idx += 128) {
            int r = idx >> 6, k = idx & 63;
            int gr = row0 + r;
            Pb[k][r] = (gr < n) ? g_pre[(size_t)gr * 512 + h * 64 + k] : 0.f;
        }
        for (int idx = t; idx < 4096; idx += 128) {
            int k = idx >> 6, c = idx & 63;
            Wgb[k][c] = Wg[k * 512 + h * 64 + c];
            Whb[k][c] = Wh[(h * 64 + k) * 64 + c];
        }
        __syncthreads();
        ull t4[4][4];
#pragma unroll
        for (int i = 0; i < 4; i++)
#pragma unroll
            for (int j = 0; j < 4; j++) t4[i][j] = 0ULL;
#pragma unroll 4
        for (int k = 0; k < 64; k++) {
            const ull* ap = (const ull*)&Pb[k][ty * 8];
            ull a0 = ap[0], a1 = ap[1], a2 = ap[2], a3 = ap[3];
            float4 bv = *(const float4*)&Wgb[k][tx * 4];
            ull b0 = pk2(bv.x, bv.x), b1 = pk2(bv.y, bv.y);
            ull b2 = pk2(bv.z, bv.z), b3 = pk2(bv.w, bv.w);
            fma2(t4[0][0], a0, b0); fma2(t4[0][1], a0, b1);
            fma2(t4[0][2], a0, b2); fma2(t4[0][3], a0, b3);
            fma2(t4[1][0], a1, b0); fma2(t4[1][1], a1, b1);
            fma2(t4[1][2], a1, b2); fma2(t4[1][3], a1, b3);
            fma2(t4[2][0], a2, b0); fma2(t4[2][1], a2, b1);
            fma2(t4[2][2], a2, b2); fma2(t4[2][3], a2, b3);
            fma2(t4[3][0], a3, b0); fma2(t4[3][1], a3, b1);
            fma2(t4[3][2], a3, b2); fma2(t4[3][3], a3, b3);
        }
#pragma unroll
        for (int j = 0; j < 4; j++) {
            float bgv = bg[h * 64 + tx * 4 + j];
#pragma unroll
            for (int i = 0; i < 4; i++) {
                float e0, e1;
                upk2(t4[i][j], e0, e1);
                Tb[tx * 4 + j][ty * 8 + 2 * i]     = fmaxf(e0 + bgv, 0.f);
                Tb[tx * 4 + j][ty * 8 + 2 * i + 1] = fmaxf(e1 + bgv, 0.f);
            }
        }
        __syncthreads();
#pragma unroll 4
        for (int k = 0; k < 64; k++) {
            const ull* ap = (const ull*)&Tb[k][ty * 8];
            ull a0 = ap[0], a1 = ap[1], a2 = ap[2], a3 = ap[3];
            float4 bv = *(const float4*)&Whb[k][tx * 4];
            ull b0 = pk2(bv.x, bv.x), b1 = pk2(bv.y, bv.y);
            ull b2 = pk2(bv.z, bv.z), b3 = pk2(bv.w, bv.w);
            fma2(acc[0][0], a0, b0); fma2(acc[0][1], a0, b1);
            fma2(acc[0][2], a0, b2); fma2(acc[0][3], a0, b3);
            fma2(acc[1][0], a1, b0); fma2(acc[1][1], a1, b1);
            fma2(acc[1][2], a1, b2); fma2(acc[1][3], a1, b3);
            fma2(acc[2][0], a2, b0); fma2(acc[2][1], a2, b1);
            fma2(acc[2][2], a2, b2); fma2(acc[2][3], a2, b3);
            fma2(acc[3][0], a3, b0); fma2(acc[3][1], a3, b1);
            fma2(acc[3][2], a3, b2); fma2(acc[3][3], a3, b3);
        }
    }
    float4 bhv = *(const float4*)&bh[tx * 4];
#pragma unroll
    for (int i = 0; i < 4; i++) {
        float x0[4], x1[4];
#pragma unroll
        for (int j = 0; j < 4; j++) upk2(acc[i][j], x0[j], x1[j]);
        int gr0 = row0 + ty * 8 + 2 * i;
        int gr1 = gr0 + 1;
        if (gr0 < n) {
            float4 v;
            v.x = fmaxf(x0[0] + bhv.x, 0.f);
            v.y = fmaxf(x0[1] + bhv.y, 0.f);
            v.z = fmaxf(x0[2] + bhv.z, 0.f);
            v.w = fmaxf(x0[3] + bhv.w, 0.f);
            *(float4*)(g_outf + gr0 * 64 + tx * 4) = v;
        }
        if (gr1 < n) {
            float4 v;
            v.x = fmaxf(x1[0] + bhv.x, 0.f);
            v.y = fmaxf(x1[1] + bhv.y, 0.f);
            v.z = fmaxf(x1[2] + bhv.z, 0.f);
            v.w = fmaxf(x1[3] + bhv.w, 0.f);
            *(float4*)(g_outf + gr1 * 64 + tx * 4) = v;
        }
    }
}

// ---------------- fused Set2Set step: LSTM + attention pool (+final) --------
__global__ void k_s2s(const float* __restrict__ W_ih,
                      const float* __restrict__ W_hh,
                      const float* __restrict__ b_ih,
                      const float* __restrict__ b_hh,
                      const float* __restrict__ W1, const float* __restrict__ b1,
                      const float* __restrict__ W2, const float* __restrict__ b2,
                      float* __restrict__ y, int do_final) {
    int b = blockIdx.x, t = threadIdx.x;  // 256 threads
    int lane = t & 31, wid = t >> 5;
    __shared__ float sq[128], shh[64], gg[256], q[64], sb[8];
    __shared__ float rr[4][64];
    __shared__ float qs2[128];
    if (t < 128) sq[t] = g_qstar[b * 128 + t];
    if (t < 64) shh[t] = g_hs[b * 64 + t];
    __syncthreads();
    {
        float acc = b_ih[t] + b_hh[t];
        const float* wr = W_ih + t * 128;
#pragma unroll 8
        for (int k = 0; k < 128; k++) acc += sq[k] * wr[k];
        const float* wr2 = W_hh + t * 64;
#pragma unroll 8
        for (int k = 0; k < 64; k++) acc += shh[k] * wr2[k];
        gg[t] = acc;
    }
    __syncthreads();
    if (t < 64) {
        float ig = 1.f / (1.f + __expf(-gg[t]));
        float fg = 1.f / (1.f + __expf(-gg[64 + t]));
        float gv = tanhf(gg[128 + t]);
        float og = 1.f / (1.f + __expf(-gg[192 + t]));
        float cn = fg * g_cs[b * 64 + t] + ig * gv;
        float hn = og * tanhf(cn);
        g_cs[b * 64 + t] = cn;
        g_hs[b * 64 + t] = hn;
        q[t] = hn;
    }
    __syncthreads();
    int s0 = g_seg[b], s1 = g_seg[b + 1];
    float mx = -1e30f;
    for (int i = s0 + t; i < s1; i += 256) {
        const float* row = g_outf + i * 64;
        float d = 0.f;
#pragma unroll
        for (int c = 0; c < 64; c += 4) {
            float4 v = *(const float4*)(row + c);
            d += v.x * q[c] + v.y * q[c + 1] + v.z * q[c + 2] + v.w * q[c + 3];
        }
        g_e2[i] = d;
        mx = fmaxf(mx, d);
    }
    for (int o = 16; o; o >>= 1) mx = fmaxf(mx, __shfl_xor_sync(0xffffffffu, mx, o));
    if (lane == 0) sb[wid] = mx;
    __syncthreads();
    mx = fmaxf(fmaxf(fmaxf(sb[0], sb[1]), fmaxf(sb[2], sb[3])),
               fmaxf(fmaxf(sb[4], sb[5]), fmaxf(sb[6], sb[7])));
    __syncthreads();
    float sm = 0.f;
    for (int i = s0 + t; i < s1; i += 256) {
        float w = __expf(g_e2[i] - mx);
        g_e2[i] = w;
        sm += w;
    }
    for (int o = 16; o; o >>= 1) sm += __shfl_xor_sync(0xffffffffu, sm, o);
    if (lane == 0) sb[wid] = sm;
    __syncthreads();
    sm = sb[0] + sb[1] + sb[2] + sb[3] + sb[4] + sb[5] + sb[6] + sb[7];
    float inv = (sm > 0.f) ? 1.f / sm : 0.f;
    __syncthreads();
    {
        int grp = t >> 6, ch = t & 63;
        float r = 0.f;
        for (int i = s0 + grp; i < s1; i += 4) r += g_e2[i] * g_outf[i * 64 + ch];
        rr[grp][ch] = r;
    }
    __syncthreads();
    if (t < 64) {
        float rt = (rr[0][t] + rr[1][t] + rr[2][t] + rr[3][t]) * inv;
        g_qstar[b * 128 + t] = q[t];
        g_qstar[b * 128 + 64 + t] = rt;
        qs2[t] = q[t];
        qs2[64 + t] = rt;
    }
    if (do_final) {
        __syncthreads();
        if (t < 64) {
            float a = b1[t];
#pragma unroll 8
            for (int k = 0; k < 128; k++) a += qs2[k] * W1[k * 64 + t];
            float z = fmaxf(a, 0.f) * W2[t];
            for (int o = 16; o; o >>= 1) z += __shfl_xor_sync(0xffffffffu, z, o);
            if (lane == 0) sb[wid] = z;
        }
        __syncthreads();
        if (t == 0) y[b] = sb[0] + sb[1] + b2[0];
    }
}

// ---------------- launcher ---------------------------------------------------
extern "C" void kernel_launch(void* const* d_in, const int* in_sizes, int n_in,
                              void* d_out, int out_size) {
    const float* x      = (const float*)d_in[0];
    const void*  edge   = d_in[1];
    const void*  batch  = d_in[2];
    const float* W0     = (const float*)d_in[3];
    const float* b0     = (const float*)d_in[4];
    const float* Wg     = (const float*)d_in[5];
    const float* att_s  = (const float*)d_in[6];
    const float* att_d  = (const float*)d_in[7];
    const float* bg     = (const float*)d_in[8];
    const float* Wh     = (const float*)d_in[9];
    const float* bh     = (const float*)d_in[10];
    const float* W_ih   = (const float*)d_in[11];
    const float* W_hh   = (const float*)d_in[12];
    const float* b_ih   = (const float*)d_in[13];
    const float* b_hh   = (const float*)d_in[14];
    const float* W1     = (const float*)d_in[15];
    const float* b1     = (const float*)d_in[16];
    const float* W2     = (const float*)d_in[17];
    const float* b2     = (const float*)d_in[18];
    float* y = (float*)d_out;

    int n = in_sizes[0] / 25;
    int E = in_sizes[1] / 2;

    k_detect<<<1, 256>>>((const int*)edge);
    k_init<<<256, 256>>>(n);
    k_convert<<<512, 256>>>(edge, batch, E, n);
    k_scanseg<<<1, 1024>>>(n);
    k_prevec<<<64, 64>>>(Wg, att_s, att_d);
    k_h0attn<<<(n + 15) / 16, 256>>>(x, W0, b0, n);
    k_scatter<<<1024, 256>>>(E, n);
    k_agg<<<(n + 7) / 8, 256>>>(n);
    k_fused<<<(n + 63) / 64, 256 / 2>>>(Wg, bg, Wh, bh, n);
    for (int it = 0; it < 3; it++) {
        k_s2s<<<BB, 256>>>(W_ih, W_hh, b_ih, b_hh, W1, b1, W2, b2, y,
                           it == 2 ? 1 : 0);
    }
}

// round 8
// speedup vs baseline: 1.0984x; 1.0984x over previous
#include <cuda_runtime.h>

#define NN 20000
#define EE 320000
#define ET (EE + NN)
#define BB 128

typedef unsigned long long ull;

__device__ __forceinline__ ull pk2(float lo, float hi) {
    ull r; asm("mov.b64 %0, {%1, %2};" : "=l"(r) : "f"(lo), "f"(hi)); return r;
}
__device__ __forceinline__ void upk2(ull v, float& lo, float& hi) {
    asm("mov.b64 {%0, %1}, %2;" : "=f"(lo), "=f"(hi) : "l"(v));
}
__device__ __forceinline__ void fma2(ull& d, ull a, ull b) {
    asm("fma.rn.f32x2 %0, %1, %2, %0;" : "+l"(d) : "l"(a), "l"(b));
}

// ---------------- scratch (device globals; no runtime allocation) ----------
__device__ int   g_src[EE], g_dst[EE], g_batch[NN];
__device__ int   g_deg[NN], g_cur[NN], g_off[NN + 1];
__device__ int   g_csr[ET];
__device__ int   g_bsum[32], g_bflag[32];
__device__ float g_h0[NN * 64];
__device__ float g_pre[(size_t)NN * 512];      // aggpre [N][h*64+k]
__device__ float g_as[NN * 8], g_ad[NN * 8];
__device__ float g_Vs[64 * 8], g_Vd[64 * 8];
__device__ float g_outf[NN * 64];
__device__ float g_e2[NN];
__device__ float g_hs[BB * 64], g_cs[BB * 64], g_qstar[BB * 128];
__device__ int   g_seg[BB + 1];

// ---------------- zero/seed-init per launch ---------------------------------
__global__ void k_init(int n) {
    int tot = 2 * n + BB * 128 + 2 * BB * 64 + 32;
    for (int i = blockIdx.x * blockDim.x + threadIdx.x; i < tot;
         i += gridDim.x * blockDim.x) {
        if (i < n) g_deg[i] = 1;            // self-loop pre-counted
        else if (i < 2 * n) g_cur[i - n] = 0;
        else {
            int j = i - 2 * n;
            if (j < BB * 128) g_qstar[j] = 0.f;
            else {
                j -= BB * 128;
                if (j < BB * 64) g_hs[j] = 0.f;
                else {
                    j -= BB * 64;
                    if (j < BB * 64) g_cs[j] = 0.f;
                    else g_bflag[j - BB * 64] = 0;
                }
            }
        }
    }
}

// ---------------- convert indices + count degrees (dtype detect inline) ----
__global__ void k_convert(const void* edge, const void* batch, int E, int n) {
    __shared__ int s_any;
    int t = threadIdx.x;
    if (t == 0) s_any = 0;
    __syncthreads();
    {
        const int* buf = (const int*)edge;
        int any = 0;
        for (int i = 2 * t + 1; i < 2048; i += 2 * 256) any |= (buf[i] != 0);
        if (any) atomicOr(&s_any, 1);
    }
    __syncthreads();
    int is64 = s_any ? 0 : 1;
    for (int i = blockIdx.x * blockDim.x + threadIdx.x; i < E;
         i += gridDim.x * blockDim.x) {
        int s, d;
        if (is64) {
            const long long* p = (const long long*)edge;
            s = (int)p[i];
            d = (int)p[(size_t)E + i];
        } else {
            const int* p = (const int*)edge;
            s = p[i];
            d = p[E + i];
        }
        g_src[i] = s;
        g_dst[i] = d;
        atomicAdd(&g_deg[d], 1);
        if (i < n) {
            g_batch[i] = is64 ? (int)((const long long*)batch)[i]
                              : ((const int*)batch)[i];
        }
    }
}

// ---------------- parallel exclusive scan (+ segment starts) ----------------
// grid 20 x 1024; each block publishes its partial, sums predecessors.
__global__ void k_scanseg(int n) {
    __shared__ int warp_sums[32];
    __shared__ int s_off;
    int b = blockIdx.x, t = threadIdx.x, lane = t & 31, wid = t >> 5;
    if (b == 0 && t <= BB) {  // segment starts for sorted batch
        if (t == BB) g_seg[BB] = n;
        else {
            int lo = 0, hi = n;
            while (lo < hi) {
                int mid = (lo + hi) >> 1;
                if (g_batch[mid] < t) lo = mid + 1;
                else hi = mid;
            }
            g_seg[t] = lo;
        }
    }
    int idx = b * 1024 + t;
    int v = (idx < n) ? g_deg[idx] : 0;
    int xv = v;
#pragma unroll
    for (int o = 1; o < 32; o <<= 1) {
        int y = __shfl_up_sync(0xffffffffu, xv, o);
        if (lane >= o) xv += y;
    }
    if (lane == 31) warp_sums[wid] = xv;
    __syncthreads();
    if (wid == 0) {
        int s = warp_sums[lane];
#pragma unroll
        for (int o = 1; o < 32; o <<= 1) {
            int y = __shfl_up_sync(0xffffffffu, s, o);
            if (lane >= o) s += y;
        }
        warp_sums[lane] = s;
    }
    __syncthreads();
    int blocktot = warp_sums[31];
    if (t == 0) {
        g_bsum[b] = blocktot;
        __threadfence();
        atomicExch(&g_bflag[b], 1);
    }
    if (wid == 0) {
        int ps = 0;
        if (lane < b) {
            while (atomicAdd(&g_bflag[lane], 0) == 0) __nanosleep(50);
            ps = g_bsum[lane];
        }
#pragma unroll
        for (int o = 16; o; o >>= 1) ps += __shfl_xor_sync(0xffffffffu, ps, o);
        if (lane == 0) s_off = ps;
    }
    __syncthreads();
    int off = s_off + (wid ? warp_sums[wid - 1] : 0);
    if (idx < n) g_off[idx] = off + xv - v;
    if (b == gridDim.x - 1 && t == 0) g_off[n] = s_off + blocktot;
}

// ---------------- Vs[k][h] = sum_c Wg[k, h*64+c] att_src[h,c] ---------------
__global__ void k_prevec(const float* __restrict__ Wg,
                         const float* __restrict__ att_src,
                         const float* __restrict__ att_dst) {
    int k = blockIdx.x, c = threadIdx.x;
    int lane = c & 31, w = c >> 5;
    __shared__ float sS[2][8], sD[2][8];
    float ps[8], pd[8];
#pragma unroll
    for (int h = 0; h < 8; h++) {
        float wv = Wg[k * 512 + h * 64 + c];
        ps[h] = wv * att_src[h * 64 + c];
        pd[h] = wv * att_dst[h * 64 + c];
    }
#pragma unroll
    for (int h = 0; h < 8; h++) {
        for (int o = 16; o; o >>= 1) {
            ps[h] += __shfl_xor_sync(0xffffffffu, ps[h], o);
            pd[h] += __shfl_xor_sync(0xffffffffu, pd[h], o);
        }
    }
    if (lane == 0) {
#pragma unroll
        for (int h = 0; h < 8; h++) { sS[w][h] = ps[h]; sD[w][h] = pd[h]; }
    }
    __syncthreads();
    if (c < 8) g_Vs[k * 8 + c] = sS[0][c] + sS[1][c];
    else if (c < 16) g_Vd[k * 8 + (c - 8)] = sD[0][c - 8] + sD[1][c - 8];
}

// ---------------- h0 = relu(x @ W0 + b0); a_s/a_d = h0 @ [Vs|Vd] ------------
__global__ void k_h0attn(const float* __restrict__ x,
                         const float* __restrict__ W0,
                         const float* __restrict__ b0, int n) {
    __shared__ float Ws[25 * 64];
    __shared__ float xs[16][26];
    __shared__ float Vsm[64][17];
    __shared__ float h0s[16][65];
    int t = threadIdx.x;  // 256
    int n0 = blockIdx.x * 16;
    for (int idx = t; idx < 1600; idx += 256) Ws[idx] = W0[idx];
    for (int idx = t; idx < 400; idx += 256) {
        int r = idx / 25, k = idx % 25;
        int gr = n0 + r;
        xs[r][k] = (gr < n) ? x[gr * 25 + k] : 0.f;
    }
    for (int idx = t; idx < 1024; idx += 256) {
        int k = idx >> 4, o = idx & 15;
        Vsm[k][o] = (o < 8) ? g_Vs[k * 8 + o] : g_Vd[k * 8 + (o - 8)];
    }
    __syncthreads();
    int j = t & 63, rb = t >> 6;
#pragma unroll
    for (int i = 0; i < 4; i++) {
        int r = rb * 4 + i;
        float acc = b0[j];
#pragma unroll
        for (int k = 0; k < 25; k++) acc += xs[r][k] * Ws[k * 64 + j];
        float v = fmaxf(acc, 0.f);
        h0s[r][j] = v;
        int gr = n0 + r;
        if (gr < n) g_h0[gr * 64 + j] = v;
    }
    __syncthreads();
    int row = t >> 4, o = t & 15;
    float acc = 0.f;
#pragma unroll 16
    for (int k = 0; k < 64; k++) acc += h0s[row][k] * Vsm[k][o];
    int gr = n0 + row;
    if (gr < n) {
        if (o < 8) g_as[gr * 8 + o] = acc;
        else       g_ad[gr * 8 + (o - 8)] = acc;
    }
}

__global__ void k_scatter(int E, int n) {
    int tot = E + n;
    for (int i = blockIdx.x * blockDim.x + threadIdx.x; i < tot;
         i += gridDim.x * blockDim.x) {
        int d = (i < E) ? g_dst[i] : (i - E);
        int s = (i < E) ? g_src[i] : (i - E);
        int pos = g_off[d] + atomicAdd(&g_cur[d], 1);
        g_csr[pos] = s;
    }
}

// ---------------- warp-per-dst softmax + aggregate in h0-space --------------
__global__ void k_agg(int n) {
    int gw = (blockIdx.x * blockDim.x + threadIdx.x) >> 5;
    int lane = threadIdx.x & 31;
    if (gw >= n) return;
    int start = g_off[gw], end = g_off[gw + 1];
    float4 adA = *(const float4*)(g_ad + gw * 8);
    float4 adB = *(const float4*)(g_ad + gw * 8 + 4);
    float ad0 = adA.x, ad1 = adA.y, ad2 = adA.z, ad3 = adA.w;
    float ad4 = adB.x, ad5 = adB.y, ad6 = adB.z, ad7 = adB.w;

    float lm[8];
#pragma unroll
    for (int h = 0; h < 8; h++) lm[h] = -1e30f;
    for (int j = start + lane; j < end; j += 32) {
        int s = g_csr[j];
        float4 aA = *(const float4*)(g_as + s * 8);
        float4 aB = *(const float4*)(g_as + s * 8 + 4);
        float e;
        e = aA.x + ad0; e = (e > 0.f) ? e : 0.2f * e; lm[0] = fmaxf(lm[0], e);
        e = aA.y + ad1; e = (e > 0.f) ? e : 0.2f * e; lm[1] = fmaxf(lm[1], e);
        e = aA.z + ad2; e = (e > 0.f) ? e : 0.2f * e; lm[2] = fmaxf(lm[2], e);
        e = aA.w + ad3; e = (e > 0.f) ? e : 0.2f * e; lm[3] = fmaxf(lm[3], e);
        e = aB.x + ad4; e = (e > 0.f) ? e : 0.2f * e; lm[4] = fmaxf(lm[4], e);
        e = aB.y + ad5; e = (e > 0.f) ? e : 0.2f * e; lm[5] = fmaxf(lm[5], e);
        e = aB.z + ad6; e = (e > 0.f) ? e : 0.2f * e; lm[6] = fmaxf(lm[6], e);
        e = aB.w + ad7; e = (e > 0.f) ? e : 0.2f * e; lm[7] = fmaxf(lm[7], e);
    }
#pragma unroll
    for (int h = 0; h < 8; h++)
        for (int o = 16; o; o >>= 1)
            lm[h] = fmaxf(lm[h], __shfl_xor_sync(0xffffffffu, lm[h], o));
    float ls[8];
#pragma unroll
    for (int h = 0; h < 8; h++) ls[h] = 0.f;
    for (int j = start + lane; j < end; j += 32) {
        int s = g_csr[j];
        float4 aA = *(const float4*)(g_as + s * 8);
        float4 aB = *(const float4*)(g_as + s * 8 + 4);
        float e;
        e = aA.x + ad0; e = (e > 0.f) ? e : 0.2f * e; ls[0] += __expf(e - lm[0]);
        e = aA.y + ad1; e = (e > 0.f) ? e : 0.2f * e; ls[1] += __expf(e - lm[1]);
        e = aA.z + ad2; e = (e > 0.f) ? e : 0.2f * e; ls[2] += __expf(e - lm[2]);
        e = aA.w + ad3; e = (e > 0.f) ? e : 0.2f * e; ls[3] += __expf(e - lm[3]);
        e = aB.x + ad4; e = (e > 0.f) ? e : 0.2f * e; ls[4] += __expf(e - lm[4]);
        e = aB.y + ad5; e = (e > 0.f) ? e : 0.2f * e; ls[5] += __expf(e - lm[5]);
        e = aB.z + ad6; e = (e > 0.f) ? e : 0.2f * e; ls[6] += __expf(e - lm[6]);
        e = aB.w + ad7; e = (e > 0.f) ? e : 0.2f * e; ls[7] += __expf(e - lm[7]);
    }
#pragma unroll
    for (int h = 0; h < 8; h++)
        for (int o = 16; o; o >>= 1)
            ls[h] += __shfl_xor_sync(0xffffffffu, ls[h], o);
    float inv[8];
#pragma unroll
    for (int h = 0; h < 8; h++) inv[h] = 1.f / ls[h];

    float advl = (lane == 0) ? ad0 : (lane == 1) ? ad1 : (lane == 2) ? ad2 :
                 (lane == 3) ? ad3 : (lane == 4) ? ad4 : (lane == 5) ? ad5 :
                 (lane == 6) ? ad6 : ad7;
    float lml  = (lane == 0) ? lm[0] : (lane == 1) ? lm[1] : (lane == 2) ? lm[2] :
                 (lane == 3) ? lm[3] : (lane == 4) ? lm[4] : (lane == 5) ? lm[5] :
                 (lane == 6) ? lm[6] : lm[7];
    float invl = (lane == 0) ? inv[0] : (lane == 1) ? inv[1] : (lane == 2) ? inv[2] :
                 (lane == 3) ? inv[3] : (lane == 4) ? inv[4] : (lane == 5) ? inv[5] :
                 (lane == 6) ? inv[6] : inv[7];

    ull acc2[8];
#pragma unroll
    for (int h = 0; h < 8; h++) acc2[h] = 0ULL;
    for (int j = start; j < end; j++) {
        int s = g_csr[j];
        float alv = 0.f;
        if (lane < 8) {
            float a = g_as[s * 8 + lane];
            float e = a + advl;
            e = (e > 0.f) ? e : 0.2f * e;
            alv = __expf(e - lml) * invl;
        }
        ull v = *(const ull*)(g_h0 + (size_t)s * 64 + lane * 2);
#pragma unroll
        for (int h = 0; h < 8; h++) {
            float a = __shfl_sync(0xffffffffu, alv, h);
            fma2(acc2[h], pk2(a, a), v);
        }
    }
#pragma unroll
    for (int h = 0; h < 8; h++)
        *(ull*)(g_pre + (size_t)gw * 512 + h * 64 + lane * 2) = acc2[h];
}

// ---------------- fused: out = relu(relu(pre (x)_h Wg_h + bg) @ Wh + bh) ----
// 128 threads; per-thread 8(rows, 4 f32x2) x 4(cols); FFMA2; T aliases P.
// Padding 68 floats (272 B row stride) keeps float4/ull accesses 16B-aligned.
__global__ void k_fused(const float* __restrict__ Wg,
                        const float* __restrict__ bg,
                        const float* __restrict__ Wh,
                        const float* __restrict__ bh, int n) {
    __shared__ float PT[64][68];   // P_h: [k][row], later T_h: [c][row]
    __shared__ float Wgb[64][68];  // Wg_h: [k][c]
    __shared__ float Whb[64][68];  // Wh_h: [c][c2]
    int row0 = blockIdx.x * 64;
    int t = threadIdx.x;  // 128
    int tx = t & 15, ty = t >> 4;  // tx: col group (4), ty: row group (8)
    ull acc[4][4];
#pragma unroll
    for (int i = 0; i < 4; i++)
#pragma unroll
        for (int j = 0; j < 4; j++) acc[i][j] = 0ULL;

    for (int h = 0; h < 8; h++) {
        __syncthreads();
        for (int idx = t; idx < 4096; idx += 128) {
            int r = idx >> 6, k = idx & 63;
            int gr = row0 + r;
            PT[k][r] = (gr < n) ? g_pre[(size_t)gr * 512 + h * 64 + k] : 0.f;
        }
        for (int idx = t; idx < 4096; idx += 128) {
            int k = idx >> 6, c = idx & 63;
            Wgb[k][c] = Wg[k * 512 + h * 64 + c];
            Whb[k][c] = Wh[(h * 64 + k) * 64 + c];
        }
        __syncthreads();
        ull t4[4][4];
#pragma unroll
        for (int i = 0; i < 4; i++)
#pragma unroll
            for (int j = 0; j < 4; j++) t4[i][j] = 0ULL;
#pragma unroll 4
        for (int k = 0; k < 64; k++) {
            const ull* ap = (const ull*)&PT[k][ty * 8];
            ull a0 = ap[0], a1 = ap[1], a2 = ap[2], a3 = ap[3];
            float4 bv = *(const float4*)&Wgb[k][tx * 4];
            ull b0 = pk2(bv.x, bv.x), b1 = pk2(bv.y, bv.y);
            ull b2 = pk2(bv.z, bv.z), b3 = pk2(bv.w, bv.w);
            fma2(t4[0][0], a0, b0); fma2(t4[0][1], a0, b1);
            fma2(t4[0][2], a0, b2); fma2(t4[0][3], a0, b3);
            fma2(t4[1][0], a1, b0); fma2(t4[1][1], a1, b1);
            fma2(t4[1][2], a1, b2); fma2(t4[1][3], a1, b3);
            fma2(t4[2][0], a2, b0); fma2(t4[2][1], a2, b1);
            fma2(t4[2][2], a2, b2); fma2(t4[2][3], a2, b3);
            fma2(t4[3][0], a3, b0); fma2(t4[3][1], a3, b1);
            fma2(t4[3][2], a3, b2); fma2(t4[3][3], a3, b3);
        }
        __syncthreads();  // PT reads done before T overwrite
#pragma unroll
        for (int j = 0; j < 4; j++) {
            float bgv = bg[h * 64 + tx * 4 + j];
#pragma unroll
            for (int i = 0; i < 4; i++) {
                float e0, e1;
                upk2(t4[i][j], e0, e1);
                PT[tx * 4 + j][ty * 8 + 2 * i]     = fmaxf(e0 + bgv, 0.f);
                PT[tx * 4 + j][ty * 8 + 2 * i + 1] = fmaxf(e1 + bgv, 0.f);
            }
        }
        __syncthreads();
#pragma unroll 4
        for (int k = 0; k < 64; k++) {
            const ull* ap = (const ull*)&PT[k][ty * 8];
            ull a0 = ap[0], a1 = ap[1], a2 = ap[2], a3 = ap[3];
            float4 bv = *(const float4*)&Whb[k][tx * 4];
            ull b0 = pk2(bv.x, bv.x), b1 = pk2(bv.y, bv.y);
            ull b2 = pk2(bv.z, bv.z), b3 = pk2(bv.w, bv.w);
            fma2(acc[0][0], a0, b0); fma2(acc[0][1], a0, b1);
            fma2(acc[0][2], a0, b2); fma2(acc[0][3], a0, b3);
            fma2(acc[1][0], a1, b0); fma2(acc[1][1], a1, b1);
            fma2(acc[1][2], a1, b2); fma2(acc[1][3], a1, b3);
            fma2(acc[2][0], a2, b0); fma2(acc[2][1], a2, b1);
            fma2(acc[2][2], a2, b2); fma2(acc[2][3], a2, b3);
            fma2(acc[3][0], a3, b0); fma2(acc[3][1], a3, b1);
            fma2(acc[3][2], a3, b2); fma2(acc[3][3], a3, b3);
        }
    }
    float4 bhv = *(const float4*)&bh[tx * 4];
#pragma unroll
    for (int i = 0; i < 4; i++) {
        float x0[4], x1[4];
#pragma unroll
        for (int j = 0; j < 4; j++) upk2(acc[i][j], x0[j], x1[j]);
        int gr0 = row0 + ty * 8 + 2 * i;
        int gr1 = gr0 + 1;
        if (gr0 < n) {
            float4 v;
            v.x = fmaxf(x0[0] + bhv.x, 0.f);
            v.y = fmaxf(x0[1] + bhv.y, 0.f);
            v.z = fmaxf(x0[2] + bhv.z, 0.f);
            v.w = fmaxf(x0[3] + bhv.w, 0.f);
            *(float4*)(g_outf + gr0 * 64 + tx * 4) = v;
        }
        if (gr1 < n) {
            float4 v;
            v.x = fmaxf(x1[0] + bhv.x, 0.f);
            v.y = fmaxf(x1[1] + bhv.y, 0.f);
            v.z = fmaxf(x1[2] + bhv.z, 0.f);
            v.w = fmaxf(x1[3] + bhv.w, 0.f);
            *(float4*)(g_outf + gr1 * 64 + tx * 4) = v;
        }
    }
}

// ---------------- fused Set2Set step: LSTM + attention pool (+final) --------
__global__ void k_s2s(const float* __restrict__ W_ih,
                      const float* __restrict__ W_hh,
                      const float* __restrict__ b_ih,
                      const float* __restrict__ b_hh,
                      const float* __restrict__ W1, const float* __restrict__ b1,
                      const float* __restrict__ W2, const float* __restrict__ b2,
                      float* __restrict__ y, int do_final) {
    int b = blockIdx.x, t = threadIdx.x;  // 256 threads
    int lane = t & 31, wid = t >> 5;
    __shared__ float sq[128], shh[64], gg[256], q[64], sb[8];
    __shared__ float rr[4][64];
    __shared__ float qs2[128];
    if (t < 128) sq[t] = g_qstar[b * 128 + t];
    if (t < 64) shh[t] = g_hs[b * 64 + t];
    __syncthreads();
    {
        float acc = b_ih[t] + b_hh[t];
        const float* wr = W_ih + t * 128;
#pragma unroll 8
        for (int k = 0; k < 128; k++) acc += sq[k] * wr[k];
        const float* wr2 = W_hh + t * 64;
#pragma unroll 8
        for (int k = 0; k < 64; k++) acc += shh[k] * wr2[k];
        gg[t] = acc;
    }
    __syncthreads();
    if (t < 64) {
        float ig = 1.f / (1.f + __expf(-gg[t]));
        float fg = 1.f / (1.f + __expf(-gg[64 + t]));
        float gv = tanhf(gg[128 + t]);
        float og = 1.f / (1.f + __expf(-gg[192 + t]));
        float cn = fg * g_cs[b * 64 + t] + ig * gv;
        float hn = og * tanhf(cn);
        g_cs[b * 64 + t] = cn;
        g_hs[b * 64 + t] = hn;
        q[t] = hn;
    }
    __syncthreads();
    int s0 = g_seg[b], s1 = g_seg[b + 1];
    float mx = -1e30f;
    for (int i = s0 + t; i < s1; i += 256) {
        const float* row = g_outf + i * 64;
        float d = 0.f;
#pragma unroll
        for (int c = 0; c < 64; c += 4) {
            float4 v = *(const float4*)(row + c);
            d += v.x * q[c] + v.y * q[c + 1] + v.z * q[c + 2] + v.w * q[c + 3];
        }
        g_e2[i] = d;
        mx = fmaxf(mx, d);
    }
    for (int o = 16; o; o >>= 1) mx = fmaxf(mx, __shfl_xor_sync(0xffffffffu, mx, o));
    if (lane == 0) sb[wid] = mx;
    __syncthreads();
    mx = fmaxf(fmaxf(fmaxf(sb[0], sb[1]), fmaxf(sb[2], sb[3])),
               fmaxf(fmaxf(sb[4], sb[5]), fmaxf(sb[6], sb[7])));
    __syncthreads();
    float sm = 0.f;
    for (int i = s0 + t; i < s1; i += 256) {
        float w = __expf(g_e2[i] - mx);
        g_e2[i] = w;
        sm += w;
    }
    for (int o = 16; o; o >>= 1) sm += __shfl_xor_sync(0xffffffffu, sm, o);
    if (lane == 0) sb[wid] = sm;
    __syncthreads();
    sm = sb[0] + sb[1] + sb[2] + sb[3] + sb[4] + sb[5] + sb[6] + sb[7];
    float inv = (sm > 0.f) ? 1.f / sm : 0.f;
    __syncthreads();
    {  // weighted read-out: 4 row groups x 4 independent accumulators
        int grp = t >> 6, ch = t & 63;
        float r0 = 0.f, r1 = 0.f, r2 = 0.f, r3 = 0.f;
        int i = s0 + grp;
        for (; i + 12 < s1; i += 16) {
            r0 += g_e2[i]      * g_outf[i * 64 + ch];
            r1 += g_e2[i + 4]  * g_outf[(i + 4) * 64 + ch];
            r2 += g_e2[i + 8]  * g_outf[(i + 8) * 64 + ch];
            r3 += g_e2[i + 12] * g_outf[(i + 12) * 64 + ch];
        }
        for (; i < s1; i += 4) r0 += g_e2[i] * g_outf[i * 64 + ch];
        rr[grp][ch] = (r0 + r1) + (r2 + r3);
    }
    __syncthreads();
    if (t < 64) {
        float rt = (rr[0][t] + rr[1][t] + rr[2][t] + rr[3][t]) * inv;
        g_qstar[b * 128 + t] = q[t];
        g_qstar[b * 128 + 64 + t] = rt;
        qs2[t] = q[t];
        qs2[64 + t] = rt;
    }
    if (do_final) {
        __syncthreads();
        if (t < 64) {
            float a = b1[t];
#pragma unroll 8
            for (int k = 0; k < 128; k++) a += qs2[k] * W1[k * 64 + t];
            float z = fmaxf(a, 0.f) * W2[t];
            for (int o = 16; o; o >>= 1) z += __shfl_xor_sync(0xffffffffu, z, o);
            if (lane == 0) sb[wid] = z;
        }
        __syncthreads();
        if (t == 0) y[b] = sb[0] + sb[1] + b2[0];
    }
}

// ---------------- launcher ---------------------------------------------------
extern "C" void kernel_launch(void* const* d_in, const int* in_sizes, int n_in,
                              void* d_out, int out_size) {
    const float* x      = (const float*)d_in[0];
    const void*  edge   = d_in[1];
    const void*  batch  = d_in[2];
    const float* W0     = (const float*)d_in[3];
    const float* b0     = (const float*)d_in[4];
    const float* Wg     = (const float*)d_in[5];
    const float* att_s  = (const float*)d_in[6];
    const float* att_d  = (const float*)d_in[7];
    const float* bg     = (const float*)d_in[8];
    const float* Wh     = (const float*)d_in[9];
    const float* bh     = (const float*)d_in[10];
    const float* W_ih   = (const float*)d_in[11];
    const float* W_hh   = (const float*)d_in[12];
    const float* b_ih   = (const float*)d_in[13];
    const float* b_hh   = (const float*)d_in[14];
    const float* W1     = (const float*)d_in[15];
    const float* b1     = (const float*)d_in[16];
    const float* W2     = (const float*)d_in[17];
    const float* b2     = (const float*)d_in[18];
    float* y = (float*)d_out;

    int n = in_sizes[0] / 25;
    int E = in_sizes[1] / 2;

    k_init<<<256, 256>>>(n);
    k_convert<<<512, 256>>>(edge, batch, E, n);
    k_scanseg<<<(n + 1023) / 1024, 1024>>>(n);
    k_prevec<<<64, 64>>>(Wg, att_s, att_d);
    k_h0attn<<<(n + 15) / 16, 256>>>(x, W0, b0, n);
    k_scatter<<<1024, 256>>>(E, n);
    k_agg<<<(n + 7) / 8, 256>>>(n);
    k_fused<<<(n + 63) / 64, 128>>>(Wg, bg, Wh, bh, n);
    for (int it = 0; it < 3; it++) {
        k_s2s<<<BB, 256>>>(W_ih, W_hh, b_ih, b_hh, W1, b1, W2, b2, y,
                           it == 2 ? 1 : 0);
    }
}

// round 10
// speedup vs baseline: 1.1075x; 1.0083x over previous
#include <cuda_runtime.h>

#define NN 20000
#define EE 320000
#define ET (EE + NN)
#define BB 128

typedef unsigned long long ull;

__device__ __forceinline__ ull pk2(float lo, float hi) {
    ull r; asm("mov.b64 %0, {%1, %2};" : "=l"(r) : "f"(lo), "f"(hi)); return r;
}
__device__ __forceinline__ void upk2(ull v, float& lo, float& hi) {
    asm("mov.b64 {%0, %1}, %2;" : "=f"(lo), "=f"(hi) : "l"(v));
}
__device__ __forceinline__ void fma2(ull& d, ull a, ull b) {
    asm("fma.rn.f32x2 %0, %1, %2, %0;" : "+l"(d) : "l"(a), "l"(b));
}

// ---------------- scratch (device globals; no runtime allocation) ----------
__device__ int   g_batch[NN];
__device__ int   g_deg[NN], g_cur[NN], g_off[NN + 1];
__device__ int   g_csr[ET];
__device__ int   g_bsum[32], g_bflag[32];
__device__ float g_h0[NN * 64];
__device__ float g_pre[(size_t)NN * 512];      // aggpre [N][h*64+k]
__device__ float g_as[NN * 8], g_ad[NN * 8];
__device__ float g_Vs[64 * 8], g_Vd[64 * 8];
__device__ float g_outf[NN * 64];
__device__ float g_e2[NN];
__device__ int   g_seg[BB + 1];

// ---------------- init (deg seed, cur, bflag) + prevec, one kernel ----------
// blocks [0,16): Vs[k][h] = sum_c Wg[k, h*64+c] att_src[h,c]  (4 k-rows/blk)
// blocks [16,...): zero/seed init.
__global__ void k_initprev(const float* __restrict__ Wg,
                           const float* __restrict__ att_src,
                           const float* __restrict__ att_dst, int n) {
    int t = threadIdx.x;  // 256
    if (blockIdx.x < 16) {
        int sub = t >> 6;          // 0..3 -> k row within block
        int c = t & 63;
        int k = blockIdx.x * 4 + sub;
        int lane = t & 31, w = t >> 5;  // warp id 0..7
        __shared__ float sS[8][8], sD[8][8];
        float ps[8], pd[8];
#pragma unroll
        for (int h = 0; h < 8; h++) {
            float wv = Wg[k * 512 + h * 64 + c];
            ps[h] = wv * att_src[h * 64 + c];
            pd[h] = wv * att_dst[h * 64 + c];
        }
#pragma unroll
        for (int h = 0; h < 8; h++) {
            for (int o = 16; o; o >>= 1) {
                ps[h] += __shfl_xor_sync(0xffffffffu, ps[h], o);
                pd[h] += __shfl_xor_sync(0xffffffffu, pd[h], o);
            }
        }
        if (lane == 0) {
#pragma unroll
            for (int h = 0; h < 8; h++) { sS[w][h] = ps[h]; sD[w][h] = pd[h]; }
        }
        __syncthreads();
        if (c < 8) g_Vs[k * 8 + c] = sS[2 * sub][c] + sS[2 * sub + 1][c];
        else if (c < 16)
            g_Vd[k * 8 + (c - 8)] = sD[2 * sub][c - 8] + sD[2 * sub + 1][c - 8];
    } else {
        int tot = 2 * n + 32;
        for (int i = (blockIdx.x - 16) * 256 + t; i < tot;
             i += (gridDim.x - 16) * 256) {
            if (i < n) g_deg[i] = 1;            // self-loop pre-counted
            else if (i < 2 * n) g_cur[i - n] = 0;
            else g_bflag[i - 2 * n] = 0;
        }
    }
}

// ---------------- histogram degrees + convert batch (dtype detect inline) --
__global__ void k_convert(const void* edge, const void* batch, int E, int n) {
    __shared__ int s_any;
    int t = threadIdx.x;
    if (t == 0) s_any = 0;
    __syncthreads();
    {
        const int* buf = (const int*)edge;
        int any = 0;
        for (int i = 2 * t + 1; i < 2048; i += 2 * 256) any |= (buf[i] != 0);
        if (any) atomicOr(&s_any, 1);
    }
    __syncthreads();
    int is64 = s_any ? 0 : 1;
    for (int i = blockIdx.x * blockDim.x + threadIdx.x; i < E;
         i += gridDim.x * blockDim.x) {
        int d = is64 ? (int)((const long long*)edge)[(size_t)E + i]
                     : ((const int*)edge)[E + i];
        atomicAdd(&g_deg[d], 1);
        if (i < n) {
            g_batch[i] = is64 ? (int)((const long long*)batch)[i]
                              : ((const int*)batch)[i];
        }
    }
}

// ---------------- parallel exclusive scan (+ segment starts) ----------------
__global__ void k_scanseg(int n) {
    __shared__ int warp_sums[32];
    __shared__ int s_off;
    int b = blockIdx.x, t = threadIdx.x, lane = t & 31, wid = t >> 5;
    if (b == 0 && t <= BB) {  // segment starts for sorted batch
        if (t == BB) g_seg[BB] = n;
        else {
            int lo = 0, hi = n;
            while (lo < hi) {
                int mid = (lo + hi) >> 1;
                if (g_batch[mid] < t) lo = mid + 1;
                else hi = mid;
            }
            g_seg[t] = lo;
        }
    }
    int idx = b * 1024 + t;
    int v = (idx < n) ? g_deg[idx] : 0;
    int xv = v;
#pragma unroll
    for (int o = 1; o < 32; o <<= 1) {
        int y = __shfl_up_sync(0xffffffffu, xv, o);
        if (lane >= o) xv += y;
    }
    if (lane == 31) warp_sums[wid] = xv;
    __syncthreads();
    if (wid == 0) {
        int s = warp_sums[lane];
#pragma unroll
        for (int o = 1; o < 32; o <<= 1) {
            int y = __shfl_up_sync(0xffffffffu, s, o);
            if (lane >= o) s += y;
        }
        warp_sums[lane] = s;
    }
    __syncthreads();
    int blocktot = warp_sums[31];
    if (t == 0) {
        g_bsum[b] = blocktot;
        __threadfence();
        atomicExch(&g_bflag[b], 1);
    }
    if (wid == 0) {
        int ps = 0;
        if (lane < b) {
            while (atomicAdd(&g_bflag[lane], 0) == 0) __nanosleep(50);
            ps = g_bsum[lane];
        }
#pragma unroll
        for (int o = 16; o; o >>= 1) ps += __shfl_xor_sync(0xffffffffu, ps, o);
        if (lane == 0) s_off = ps;
    }
    __syncthreads();
    int off = s_off + (wid ? warp_sums[wid - 1] : 0);
    if (idx < n) g_off[idx] = off + xv - v;
    if (b == gridDim.x - 1 && t == 0) g_off[n] = s_off + blocktot;
}

// ---------------- h0 = relu(x @ W0 + b0); a_s/a_d = h0 @ [Vs|Vd] ------------
__global__ void k_h0attn(const float* __restrict__ x,
                         const float* __restrict__ W0,
                         const float* __restrict__ b0, int n) {
    __shared__ float Ws[25 * 64];
    __shared__ float xs[16][26];
    __shared__ float Vsm[64][17];
    __shared__ float h0s[16][65];
    int t = threadIdx.x;  // 256
    int n0 = blockIdx.x * 16;
    for (int idx = t; idx < 1600; idx += 256) Ws[idx] = W0[idx];
    for (int idx = t; idx < 400; idx += 256) {
        int r = idx / 25, k = idx % 25;
        int gr = n0 + r;
        xs[r][k] = (gr < n) ? x[gr * 25 + k] : 0.f;
    }
    for (int idx = t; idx < 1024; idx += 256) {
        int k = idx >> 4, o = idx & 15;
        Vsm[k][o] = (o < 8) ? g_Vs[k * 8 + o] : g_Vd[k * 8 + (o - 8)];
    }
    __syncthreads();
    int j = t & 63, rb = t >> 6;
#pragma unroll
    for (int i = 0; i < 4; i++) {
        int r = rb * 4 + i;
        float acc = b0[j];
#pragma unroll
        for (int k = 0; k < 25; k++) acc += xs[r][k] * Ws[k * 64 + j];
        float v = fmaxf(acc, 0.f);
        h0s[r][j] = v;
        int gr = n0 + r;
        if (gr < n) g_h0[gr * 64 + j] = v;
    }
    __syncthreads();
    int row = t >> 4, o = t & 15;
    float acc = 0.f;
#pragma unroll 16
    for (int k = 0; k < 64; k++) acc += h0s[row][k] * Vsm[k][o];
    int gr = n0 + row;
    if (gr < n) {
        if (o < 8) g_as[gr * 8 + o] = acc;
        else       g_ad[gr * 8 + (o - 8)] = acc;
    }
}

// ---------------- scatter edges into CSR (reads raw edge, inline detect) ----
__global__ void k_scatter(const void* edge, int E, int n) {
    __shared__ int s_any;
    int t = threadIdx.x;
    if (t == 0) s_any = 0;
    __syncthreads();
    {
        const int* buf = (const int*)edge;
        int any = 0;
        for (int i = 2 * t + 1; i < 2048; i += 2 * 256) any |= (buf[i] != 0);
        if (any) atomicOr(&s_any, 1);
    }
    __syncthreads();
    int is64 = s_any ? 0 : 1;
    int tot = E + n;
    for (int i = blockIdx.x * blockDim.x + threadIdx.x; i < tot;
         i += gridDim.x * blockDim.x) {
        int s, d;
        if (i < E) {
            if (is64) {
                const long long* p = (const long long*)edge;
                s = (int)p[i];
                d = (int)p[(size_t)E + i];
            } else {
                const int* p = (const int*)edge;
                s = p[i];
                d = p[E + i];
            }
        } else {
            s = d = i - E;
        }
        int pos = g_off[d] + atomicAdd(&g_cur[d], 1);
        g_csr[pos] = s;
    }
}

// ---------------- warp-per-dst softmax + aggregate in h0-space --------------
__global__ void k_agg(int n) {
    int gw = (blockIdx.x * blockDim.x + threadIdx.x) >> 5;
    int lane = threadIdx.x & 31;
    if (gw >= n) return;
    int start = g_off[gw], end = g_off[gw + 1];
    float4 adA = *(const float4*)(g_ad + gw * 8);
    float4 adB = *(const float4*)(g_ad + gw * 8 + 4);
    float ad0 = adA.x, ad1 = adA.y, ad2 = adA.z, ad3 = adA.w;
    float ad4 = adB.x, ad5 = adB.y, ad6 = adB.z, ad7 = adB.w;

    float lm[8];
#pragma unroll
    for (int h = 0; h < 8; h++) lm[h] = -1e30f;
    for (int j = start + lane; j < end; j += 32) {
        int s = g_csr[j];
        float4 aA = *(const float4*)(g_as + s * 8);
        float4 aB = *(const float4*)(g_as + s * 8 + 4);
        float e;
        e = aA.x + ad0; e = (e > 0.f) ? e : 0.2f * e; lm[0] = fmaxf(lm[0], e);
        e = aA.y + ad1; e = (e > 0.f) ? e : 0.2f * e; lm[1] = fmaxf(lm[1], e);
        e = aA.z + ad2; e = (e > 0.f) ? e : 0.2f * e; lm[2] = fmaxf(lm[2], e);
        e = aA.w + ad3; e = (e > 0.f) ? e : 0.2f * e; lm[3] = fmaxf(lm[3], e);
        e = aB.x + ad4; e = (e > 0.f) ? e : 0.2f * e; lm[4] = fmaxf(lm[4], e);
        e = aB.y + ad5; e = (e > 0.f) ? e : 0.2f * e; lm[5] = fmaxf(lm[5], e);
        e = aB.z + ad6; e = (e > 0.f) ? e : 0.2f * e; lm[6] = fmaxf(lm[6], e);
        e = aB.w + ad7; e = (e > 0.f) ? e : 0.2f * e; lm[7] = fmaxf(lm[7], e);
    }
#pragma unroll
    for (int h = 0; h < 8; h++)
        for (int o = 16; o; o >>= 1)
            lm[h] = fmaxf(lm[h], __shfl_xor_sync(0xffffffffu, lm[h], o));
    float ls[8];
#pragma unroll
    for (int h = 0; h < 8; h++) ls[h] = 0.f;
    for (int j = start + lane; j < end; j += 32) {
        int s = g_csr[j];
        float4 aA = *(const float4*)(g_as + s * 8);
        float4 aB = *(const float4*)(g_as + s * 8 + 4);
        float e;
        e = aA.x + ad0; e = (e > 0.f) ? e : 0.2f * e; ls[0] += __expf(e - lm[0]);
        e = aA.y + ad1; e = (e > 0.f) ? e : 0.2f * e; ls[1] += __expf(e - lm[1]);
        e = aA.z + ad2; e = (e > 0.f) ? e : 0.2f * e; ls[2] += __expf(e - lm[2]);
        e = aA.w + ad3; e = (e > 0.f) ? e : 0.2f * e; ls[3] += __expf(e - lm[3]);
        e = aB.x + ad4; e = (e > 0.f) ? e : 0.2f * e; ls[4] += __expf(e - lm[4]);
        e = aB.y + ad5; e = (e > 0.f) ? e : 0.2f * e; ls[5] += __expf(e - lm[5]);
        e = aB.z + ad6; e = (e > 0.f) ? e : 0.2f * e; ls[6] += __expf(e - lm[6]);
        e = aB.w + ad7; e = (e > 0.f) ? e : 0.2f * e; ls[7] += __expf(e - lm[7]);
    }
#pragma unroll
    for (int h = 0; h < 8; h++)
        for (int o = 16; o; o >>= 1)
            ls[h] += __shfl_xor_sync(0xffffffffu, ls[h], o);
    float inv[8];
#pragma unroll
    for (int h = 0; h < 8; h++) inv[h] = 1.f / ls[h];

    float advl = (lane == 0) ? ad0 : (lane == 1) ? ad1 : (lane == 2) ? ad2 :
                 (lane == 3) ? ad3 : (lane == 4) ? ad4 : (lane == 5) ? ad5 :
                 (lane == 6) ? ad6 : ad7;
    float lml  = (lane == 0) ? lm[0] : (lane == 1) ? lm[1] : (lane == 2) ? lm[2] :
                 (lane == 3) ? lm[3] : (lane == 4) ? lm[4] : (lane == 5) ? lm[5] :
                 (lane == 6) ? lm[6] : lm[7];
    float invl = (lane == 0) ? inv[0] : (lane == 1) ? inv[1] : (lane == 2) ? inv[2] :
                 (lane == 3) ? inv[3] : (lane == 4) ? inv[4] : (lane == 5) ? inv[5] :
                 (lane == 6) ? inv[6] : inv[7];

    ull acc2[8];
#pragma unroll
    for (int h = 0; h < 8; h++) acc2[h] = 0ULL;
    for (int j = start; j < end; j++) {
        int s = g_csr[j];
        float alv = 0.f;
        if (lane < 8) {
            float a = g_as[s * 8 + lane];
            float e = a + advl;
            e = (e > 0.f) ? e : 0.2f * e;
            alv = __expf(e - lml) * invl;
        }
        ull v = *(const ull*)(g_h0 + (size_t)s * 64 + lane * 2);
#pragma unroll
        for (int h = 0; h < 8; h++) {
            float a = __shfl_sync(0xffffffffu, alv, h);
            fma2(acc2[h], pk2(a, a), v);
        }
    }
#pragma unroll
    for (int h = 0; h < 8; h++)
        *(ull*)(g_pre + (size_t)gw * 512 + h * 64 + lane * 2) = acc2[h];
}

// ---------------- fused: out = relu(relu(pre (x)_h Wg_h + bg) @ Wh + bh) ----
__global__ void k_fused(const float* __restrict__ Wg,
                        const float* __restrict__ bg,
                        const float* __restrict__ Wh,
                        const float* __restrict__ bh, int n) {
    __shared__ float PT[64][68];   // P_h: [k][row], later T_h: [c][row]
    __shared__ float Wgb[64][68];  // Wg_h: [k][c]
    __shared__ float Whb[64][68];  // Wh_h: [c][c2]
    int row0 = blockIdx.x * 64;
    int t = threadIdx.x;  // 128
    int tx = t & 15, ty = t >> 4;
    ull acc[4][4];
#pragma unroll
    for (int i = 0; i < 4; i++)
#pragma unroll
        for (int j = 0; j < 4; j++) acc[i][j] = 0ULL;

    for (int h = 0; h < 8; h++) {
        __syncthreads();
        for (int idx = t; idx < 4096; idx += 128) {
            int r = idx >> 6, k = idx & 63;
            int gr = row0 + r;
            PT[k][r] = (gr < n) ? g_pre[(size_t)gr * 512 + h * 64 + k] : 0.f;
        }
        for (int idx = t; idx < 4096; idx += 128) {
            int k = idx >> 6, c = idx & 63;
            Wgb[k][c] = Wg[k * 512 + h * 64 + c];
            Whb[k][c] = Wh[(h * 64 + k) * 64 + c];
        }
        __syncthreads();
        ull t4[4][4];
#pragma unroll
        for (int i = 0; i < 4; i++)
#pragma unroll
            for (int j = 0; j < 4; j++) t4[i][j] = 0ULL;
#pragma unroll 4
        for (int k = 0; k < 64; k++) {
            const ull* ap = (const ull*)&PT[k][ty * 8];
            ull a0 = ap[0], a1 = ap[1], a2 = ap[2], a3 = ap[3];
            float4 bv = *(const float4*)&Wgb[k][tx * 4];
            ull b0 = pk2(bv.x, bv.x), b1 = pk2(bv.y, bv.y);
            ull b2 = pk2(bv.z, bv.z), b3 = pk2(bv.w, bv.w);
            fma2(t4[0][0], a0, b0); fma2(t4[0][1], a0, b1);
            fma2(t4[0][2], a0, b2); fma2(t4[0][3], a0, b3);
            fma2(t4[1][0], a1, b0); fma2(t4[1][1], a1, b1);
            fma2(t4[1][2], a1, b2); fma2(t4[1][3], a1, b3);
            fma2(t4[2][0], a2, b0); fma2(t4[2][1], a2, b1);
            fma2(t4[2][2], a2, b2); fma2(t4[2][3], a2, b3);
            fma2(t4[3][0], a3, b0); fma2(t4[3][1], a3, b1);
            fma2(t4[3][2], a3, b2); fma2(t4[3][3], a3, b3);
        }
        __syncthreads();  // PT reads done before T overwrite
#pragma unroll
        for (int j = 0; j < 4; j++) {
            float bgv = bg[h * 64 + tx * 4 + j];
#pragma unroll
            for (int i = 0; i < 4; i++) {
                float e0, e1;
                upk2(t4[i][j], e0, e1);
                PT[tx * 4 + j][ty * 8 + 2 * i]     = fmaxf(e0 + bgv, 0.f);
                PT[tx * 4 + j][ty * 8 + 2 * i + 1] = fmaxf(e1 + bgv, 0.f);
            }
        }
        __syncthreads();
#pragma unroll 4
        for (int k = 0; k < 64; k++) {
            const ull* ap = (const ull*)&PT[k][ty * 8];
            ull a0 = ap[0], a1 = ap[1], a2 = ap[2], a3 = ap[3];
            float4 bv = *(const float4*)&Whb[k][tx * 4];
            ull b0 = pk2(bv.x, bv.x), b1 = pk2(bv.y, bv.y);
            ull b2 = pk2(bv.z, bv.z), b3 = pk2(bv.w, bv.w);
            fma2(acc[0][0], a0, b0); fma2(acc[0][1], a0, b1);
            fma2(acc[0][2], a0, b2); fma2(acc[0][3], a0, b3);
            fma2(acc[1][0], a1, b0); fma2(acc[1][1], a1, b1);
            fma2(acc[1][2], a1, b2); fma2(acc[1][3], a1, b3);
            fma2(acc[2][0], a2, b0); fma2(acc[2][1], a2, b1);
            fma2(acc[2][2], a2, b2); fma2(acc[2][3], a2, b3);
            fma2(acc[3][0], a3, b0); fma2(acc[3][1], a3, b1);
            fma2(acc[3][2], a3, b2); fma2(acc[3][3], a3, b3);
        }
    }
    float4 bhv = *(const float4*)&bh[tx * 4];
#pragma unroll
    for (int i = 0; i < 4; i++) {
        float x0[4], x1[4];
#pragma unroll
        for (int j = 0; j < 4; j++) upk2(acc[i][j], x0[j], x1[j]);
        int gr0 = row0 + ty * 8 + 2 * i;
        int gr1 = gr0 + 1;
        if (gr0 < n) {
            float4 v;
            v.x = fmaxf(x0[0] + bhv.x, 0.f);
            v.y = fmaxf(x0[1] + bhv.y, 0.f);
            v.z = fmaxf(x0[2] + bhv.z, 0.f);
            v.w = fmaxf(x0[3] + bhv.w, 0.f);
            *(float4*)(g_outf + gr0 * 64 + tx * 4) = v;
        }
        if (gr1 < n) {
            float4 v;
            v.x = fmaxf(x1[0] + bhv.x, 0.f);
            v.y = fmaxf(x1[1] + bhv.y, 0.f);
            v.z = fmaxf(x1[2] + bhv.z, 0.f);
            v.w = fmaxf(x1[3] + bhv.w, 0.f);
            *(float4*)(g_outf + gr1 * 64 + tx * 4) = v;
        }
    }
}

// ---------------- Set2Set: all 3 iterations + final MLP in ONE kernel -------
// One block per graph; LSTM state and q_star live in smem across iterations.
__global__ void k_s2s(const float* __restrict__ W_ih,
                      const float* __restrict__ W_hh,
                      const float* __restrict__ b_ih,
                      const float* __restrict__ b_hh,
                      const float* __restrict__ W1, const float* __restrict__ b1,
                      const float* __restrict__ W2, const float* __restrict__ b2,
                      float* __restrict__ y) {
    int b = blockIdx.x, t = threadIdx.x;  // 256 threads
    int lane = t & 31, wid = t >> 5;
    __shared__ float qstar[128], hh[64], cc[64], gg[256], q[64], sb[8];
    __shared__ float rr[4][64];
    if (t < 128) qstar[t] = 0.f;
    if (t < 64) { hh[t] = 0.f; cc[t] = 0.f; }
    __syncthreads();
    int s0 = g_seg[b], s1 = g_seg[b + 1];

    for (int it = 0; it < 3; it++) {
        // LSTM gates
        {
            float acc = b_ih[t] + b_hh[t];
            const float* wr = W_ih + t * 128;
#pragma unroll 8
            for (int k = 0; k < 128; k++) acc += qstar[k] * wr[k];
            const float* wr2 = W_hh + t * 64;
#pragma unroll 8
            for (int k = 0; k < 64; k++) acc += hh[k] * wr2[k];
            gg[t] = acc;
        }
        __syncthreads();
        if (t < 64) {
            float ig = 1.f / (1.f + __expf(-gg[t]));
            float fg = 1.f / (1.f + __expf(-gg[64 + t]));
            float gv = tanhf(gg[128 + t]);
            float og = 1.f / (1.f + __expf(-gg[192 + t]));
            float cn = fg * cc[t] + ig * gv;
            float hn = og * tanhf(cn);
            cc[t] = cn;
            hh[t] = hn;
            q[t] = hn;
        }
        __syncthreads();
        // attention scores + max
        float mx = -1e30f;
        for (int i = s0 + t; i < s1; i += 256) {
            const float* row = g_outf + i * 64;
            float d = 0.f;
#pragma unroll
            for (int c = 0; c < 64; c += 4) {
                float4 v = *(const float4*)(row + c);
                d += v.x * q[c] + v.y * q[c + 1] + v.z * q[c + 2] + v.w * q[c + 3];
            }
            g_e2[i] = d;
            mx = fmaxf(mx, d);
        }
        for (int o = 16; o; o >>= 1)
            mx = fmaxf(mx, __shfl_xor_sync(0xffffffffu, mx, o));
        if (lane == 0) sb[wid] = mx;
        __syncthreads();
        mx = fmaxf(fmaxf(fmaxf(sb[0], sb[1]), fmaxf(sb[2], sb[3])),
                   fmaxf(fmaxf(sb[4], sb[5]), fmaxf(sb[6], sb[7])));
        __syncthreads();
        // exp + sum
        float sm = 0.f;
        for (int i = s0 + t; i < s1; i += 256) {
            float w = __expf(g_e2[i] - mx);
            g_e2[i] = w;
            sm += w;
        }
        for (int o = 16; o; o >>= 1) sm += __shfl_xor_sync(0xffffffffu, sm, o);
        if (lane == 0) sb[wid] = sm;
        __syncthreads();
        sm = sb[0] + sb[1] + sb[2] + sb[3] + sb[4] + sb[5] + sb[6] + sb[7];
        float inv = (sm > 0.f) ? 1.f / sm : 0.f;
        __syncthreads();
        // weighted read-out
        {
            int grp = t >> 6, ch = t & 63;
            float r0 = 0.f, r1 = 0.f, r2 = 0.f, r3 = 0.f;
            int i = s0 + grp;
            for (; i + 12 < s1; i += 16) {
                r0 += g_e2[i]      * g_outf[i * 64 + ch];
                r1 += g_e2[i + 4]  * g_outf[(i + 4) * 64 + ch];
                r2 += g_e2[i + 8]  * g_outf[(i + 8) * 64 + ch];
                r3 += g_e2[i + 12] * g_outf[(i + 12) * 64 + ch];
            }
            for (; i < s1; i += 4) r0 += g_e2[i] * g_outf[i * 64 + ch];
            rr[grp][ch] = (r0 + r1) + (r2 + r3);
        }
        __syncthreads();
        if (t < 64) {
            float rt = (rr[0][t] + rr[1][t] + rr[2][t] + rr[3][t]) * inv;
            qstar[t] = q[t];
            qstar[64 + t] = rt;
        }
        __syncthreads();
    }
    // final MLP: y = relu(q_star@W1+b1)@W2 + b2
    if (t < 64) {
        float a = b1[t];
#pragma unroll 8
        for (int k = 0; k < 128; k++) a += qstar[k] * W1[k * 64 + t];
        float z = fmaxf(a, 0.f) * W2[t];
        for (int o = 16; o; o >>= 1) z += __shfl_xor_sync(0xffffffffu, z, o);
        if (lane == 0) sb[wid] = z;
    }
    __syncthreads();
    if (t == 0) y[b] = sb[0] + sb[1] + b2[0];
}

// ---------------- launcher ---------------------------------------------------
extern "C" void kernel_launch(void* const* d_in, const int* in_sizes, int n_in,
                              void* d_out, int out_size) {
    const float* x      = (const float*)d_in[0];
    const void*  edge   = d_in[1];
    const void*  batch  = d_in[2];
    const float* W0     = (const float*)d_in[3];
    const float* b0     = (const float*)d_in[4];
    const float* Wg     = (const float*)d_in[5];
    const float* att_s  = (const float*)d_in[6];
    const float* att_d  = (const float*)d_in[7];
    const float* bg     = (const float*)d_in[8];
    const float* Wh     = (const float*)d_in[9];
    const float* bh     = (const float*)d_in[10];
    const float* W_ih   = (const float*)d_in[11];
    const float* W_hh   = (const float*)d_in[12];
    const float* b_ih   = (const float*)d_in[13];
    const float* b_hh   = (const float*)d_in[14];
    const float* W1     = (const float*)d_in[15];
    const float* b1     = (const float*)d_in[16];
    const float* W2     = (const float*)d_in[17];
    const float* b2     = (const float*)d_in[18];
    float* y = (float*)d_out;

    int n = in_sizes[0] / 25;
    int E = in_sizes[1] / 2;

    k_initprev<<<176, 256>>>(Wg, att_s, att_d, n);
    k_convert<<<512, 256>>>(edge, batch, E, n);
    k_scanseg<<<(n + 1023) / 1024, 1024>>>(n);
    k_h0attn<<<(n + 15) / 16, 256>>>(x, W0, b0, n);
    k_scatter<<<1024, 256>>>(edge, E, n);
    k_agg<<<(n + 7) / 8, 256>>>(n);
    k_fused<<<(n + 63) / 64, 128>>>(Wg, bg, Wh, bh, n);
    k_s2s<<<BB, 256>>>(W_ih, W_hh, b_ih, b_hh, W1, b1, W2, b2, y);
}

// round 11
// speedup vs baseline: 1.1254x; 1.0162x over previous
#include <cuda_runtime.h>

#define NN 20000
#define EE 320000
#define ET (EE + NN)
#define BB 128
#define NBLK 148

typedef unsigned long long ull;

__device__ __forceinline__ ull pk2(float lo, float hi) {
    ull r; asm("mov.b64 %0, {%1, %2};" : "=l"(r) : "f"(lo), "f"(hi)); return r;
}
__device__ __forceinline__ void upk2(ull v, float& lo, float& hi) {
    asm("mov.b64 {%0, %1}, %2;" : "=f"(lo), "=f"(hi) : "l"(v));
}
__device__ __forceinline__ void fma2(ull& d, ull a, ull b) {
    asm("fma.rn.f32x2 %0, %1, %2, %0;" : "+l"(d) : "l"(a), "l"(b));
}

// ---------------- scratch (device globals; no runtime allocation) ----------
__device__ int   g_batch[NN];
__device__ int   g_deg[NN], g_cur[NN], g_off[NN + 1];
__device__ int   g_csr[ET];
__device__ int   g_bsum[32], g_bflag[32];
__device__ volatile unsigned g_gsync[3];   // monotonic barrier counters
__device__ float g_h0[NN * 64];
__device__ float g_pre[(size_t)NN * 512];  // aggpre [N][h*64+k]
__device__ float g_as[NN * 8], g_ad[NN * 8];
__device__ float g_Vs[64 * 8], g_Vd[64 * 8];
__device__ float g_outf[NN * 64];
__device__ float g_e2[NN];
__device__ int   g_seg[BB + 1];

// non-resetting grid barrier: arrivals are monotonic across replays;
// target = next multiple of NBLK above my ticket. All NBLK blocks co-resident.
__device__ __forceinline__ void gsync(int s) {
    __syncthreads();
    if (threadIdx.x == 0) {
        __threadfence();
        unsigned old = atomicAdd((unsigned*)&g_gsync[s], 1u);
        unsigned target = old - (old % (unsigned)NBLK) + (unsigned)NBLK;
        while (g_gsync[s] < target) __nanosleep(40);
        __threadfence();
    }
    __syncthreads();
}

// ---------------- persistent CSR build: init+prevec | hist | scan | scatter -
__global__ void __launch_bounds__(1024, 1)
k_csrbuild(const void* edge, const void* batch,
           const float* __restrict__ Wg,
           const float* __restrict__ att_src,
           const float* __restrict__ att_dst, int E, int n) {
    __shared__ float sS[32][8], sD[32][8];
    __shared__ int warp_sums[32];
    __shared__ int s_off, s_any;
    int b = blockIdx.x, t = threadIdx.x;
    int lane = t & 31, wid = t >> 5;

    // ---- phase 0: prevec (blocks 0-3) + zero init (blocks 4+) ----
    if (b < 4) {
        int r = t >> 6;            // row within block 0..15
        int k = b * 16 + r;
        int c = t & 63;
        float ps[8], pd[8];
#pragma unroll
        for (int h = 0; h < 8; h++) {
            float wv = Wg[k * 512 + h * 64 + c];
            ps[h] = wv * att_src[h * 64 + c];
            pd[h] = wv * att_dst[h * 64 + c];
        }
#pragma unroll
        for (int h = 0; h < 8; h++) {
            for (int o = 16; o; o >>= 1) {
                ps[h] += __shfl_xor_sync(0xffffffffu, ps[h], o);
                pd[h] += __shfl_xor_sync(0xffffffffu, pd[h], o);
            }
        }
        if (lane == 0) {
#pragma unroll
            for (int h = 0; h < 8; h++) { sS[wid][h] = ps[h]; sD[wid][h] = pd[h]; }
        }
        __syncthreads();
        if (c < 8) g_Vs[k * 8 + c] = sS[2 * r][c] + sS[2 * r + 1][c];
        else if (c < 16)
            g_Vd[k * 8 + (c - 8)] = sD[2 * r][c - 8] + sD[2 * r + 1][c - 8];
    } else {
        int tot = 2 * n + 32;
        for (int i = (b - 4) * 1024 + t; i < tot; i += (NBLK - 4) * 1024) {
            if (i < n) g_deg[i] = 0;
            else if (i < 2 * n) g_cur[i - n] = 0;
            else g_bflag[i - 2 * n] = 0;
        }
    }
    gsync(0);

    // ---- dtype detect (per block, from first 2KB of edge buffer) ----
    if (t == 0) s_any = 0;
    __syncthreads();
    {
        const int* buf = (const int*)edge;
        int any = 0;
        for (int i = 2 * t + 1; i < 2048; i += 2 * 1024) any |= (buf[i] != 0);
        if (any) atomicOr(&s_any, 1);
    }
    __syncthreads();
    int is64 = s_any ? 0 : 1;

    // ---- phase 1: degree histogram + batch convert ----
    for (int i = b * 1024 + t; i < E; i += NBLK * 1024) {
        int d = is64 ? (int)((const long long*)edge)[(size_t)E + i]
                     : ((const int*)edge)[E + i];
        atomicAdd(&g_deg[d], 1);
        if (i < n) {
            g_batch[i] = is64 ? (int)((const long long*)batch)[i]
                              : ((const int*)batch)[i];
        }
    }
    gsync(1);

    // ---- phase 2: exclusive scan over (deg+1) + segment starts ----
    int ntiles = (n + 1023) / 1024;
    if (b < ntiles) {
        int idx = b * 1024 + t;
        int v = (idx < n) ? g_deg[idx] + 1 : 0;   // +1 = self-loop
        int xv = v;
#pragma unroll
        for (int o = 1; o < 32; o <<= 1) {
            int y = __shfl_up_sync(0xffffffffu, xv, o);
            if (lane >= o) xv += y;
        }
        if (lane == 31) warp_sums[wid] = xv;
        __syncthreads();
        if (wid == 0) {
            int s = warp_sums[lane];
#pragma unroll
            for (int o = 1; o < 32; o <<= 1) {
                int y = __shfl_up_sync(0xffffffffu, s, o);
                if (lane >= o) s += y;
            }
            warp_sums[lane] = s;
        }
        __syncthreads();
        int blocktot = warp_sums[31];
        if (t == 0) {
            g_bsum[b] = blocktot;
            __threadfence();
            atomicExch(&g_bflag[b], 1);
        }
        if (wid == 0) {
            int ps = 0;
            if (lane < b) {
                while (atomicAdd(&g_bflag[lane], 0) == 0) __nanosleep(40);
                ps = g_bsum[lane];
            }
#pragma unroll
            for (int o = 16; o; o >>= 1) ps += __shfl_xor_sync(0xffffffffu, ps, o);
            if (lane == 0) s_off = ps;
        }
        __syncthreads();
        int off = s_off + (wid ? warp_sums[wid - 1] : 0);
        if (idx < n) g_off[idx] = off + xv - v;
        if (b == ntiles - 1 && t == 0) g_off[n] = s_off + blocktot;
    } else if (b == ntiles) {
        if (t <= BB) {  // segment starts for sorted batch
            if (t == BB) g_seg[BB] = n;
            else {
                int lo = 0, hi = n;
                while (lo < hi) {
                    int mid = (lo + hi) >> 1;
                    if (g_batch[mid] < t) lo = mid + 1;
                    else hi = mid;
                }
                g_seg[t] = lo;
            }
        }
    }
    gsync(2);

    // ---- phase 3: scatter edges + self-loops into CSR ----
    int tot = E + n;
    for (int i = b * 1024 + t; i < tot; i += NBLK * 1024) {
        int s, d;
        if (i < E) {
            if (is64) {
                const long long* p = (const long long*)edge;
                s = (int)p[i];
                d = (int)p[(size_t)E + i];
            } else {
                const int* p = (const int*)edge;
                s = p[i];
                d = p[E + i];
            }
        } else {
            s = d = i - E;
        }
        int pos = g_off[d] + atomicAdd(&g_cur[d], 1);
        g_csr[pos] = s;
    }
}

// ---------------- h0 = relu(x @ W0 + b0); a_s/a_d = h0 @ [Vs|Vd] ------------
__global__ void k_h0attn(const float* __restrict__ x,
                         const float* __restrict__ W0,
                         const float* __restrict__ b0, int n) {
    __shared__ float Ws[25 * 64];
    __shared__ float xs[16][26];
    __shared__ float Vsm[64][17];
    __shared__ float h0s[16][65];
    int t = threadIdx.x;  // 256
    int n0 = blockIdx.x * 16;
    for (int idx = t; idx < 1600; idx += 256) Ws[idx] = W0[idx];
    for (int idx = t; idx < 400; idx += 256) {
        int r = idx / 25, k = idx % 25;
        int gr = n0 + r;
        xs[r][k] = (gr < n) ? x[gr * 25 + k] : 0.f;
    }
    for (int idx = t; idx < 1024; idx += 256) {
        int k = idx >> 4, o = idx & 15;
        Vsm[k][o] = (o < 8) ? g_Vs[k * 8 + o] : g_Vd[k * 8 + (o - 8)];
    }
    __syncthreads();
    int j = t & 63, rb = t >> 6;
#pragma unroll
    for (int i = 0; i < 4; i++) {
        int r = rb * 4 + i;
        float acc = b0[j];
#pragma unroll
        for (int k = 0; k < 25; k++) acc += xs[r][k] * Ws[k * 64 + j];
        float v = fmaxf(acc, 0.f);
        h0s[r][j] = v;
        int gr = n0 + r;
        if (gr < n) g_h0[gr * 64 + j] = v;
    }
    __syncthreads();
    int row = t >> 4, o = t & 15;
    float acc = 0.f;
#pragma unroll 16
    for (int k = 0; k < 64; k++) acc += h0s[row][k] * Vsm[k][o];
    int gr = n0 + row;
    if (gr < n) {
        if (o < 8) g_as[gr * 8 + o] = acc;
        else       g_ad[gr * 8 + (o - 8)] = acc;
    }
}

// ---------------- warp-per-dst softmax + aggregate in h0-space --------------
__global__ void k_agg(int n) {
    int gw = (blockIdx.x * blockDim.x + threadIdx.x) >> 5;
    int lane = threadIdx.x & 31;
    if (gw >= n) return;
    int start = g_off[gw], end = g_off[gw + 1];
    float4 adA = *(const float4*)(g_ad + gw * 8);
    float4 adB = *(const float4*)(g_ad + gw * 8 + 4);
    float ad0 = adA.x, ad1 = adA.y, ad2 = adA.z, ad3 = adA.w;
    float ad4 = adB.x, ad5 = adB.y, ad6 = adB.z, ad7 = adB.w;

    float lm[8];
#pragma unroll
    for (int h = 0; h < 8; h++) lm[h] = -1e30f;
    for (int j = start + lane; j < end; j += 32) {
        int s = g_csr[j];
        float4 aA = *(const float4*)(g_as + s * 8);
        float4 aB = *(const float4*)(g_as + s * 8 + 4);
        float e;
        e = aA.x + ad0; e = (e > 0.f) ? e : 0.2f * e; lm[0] = fmaxf(lm[0], e);
        e = aA.y + ad1; e = (e > 0.f) ? e : 0.2f * e; lm[1] = fmaxf(lm[1], e);
        e = aA.z + ad2; e = (e > 0.f) ? e : 0.2f * e; lm[2] = fmaxf(lm[2], e);
        e = aA.w + ad3; e = (e > 0.f) ? e : 0.2f * e; lm[3] = fmaxf(lm[3], e);
        e = aB.x + ad4; e = (e > 0.f) ? e : 0.2f * e; lm[4] = fmaxf(lm[4], e);
        e = aB.y + ad5; e = (e > 0.f) ? e : 0.2f * e; lm[5] = fmaxf(lm[5], e);
        e = aB.z + ad6; e = (e > 0.f) ? e : 0.2f * e; lm[6] = fmaxf(lm[6], e);
        e = aB.w + ad7; e = (e > 0.f) ? e : 0.2f * e; lm[7] = fmaxf(lm[7], e);
    }
#pragma unroll
    for (int h = 0; h < 8; h++)
        for (int o = 16; o; o >>= 1)
            lm[h] = fmaxf(lm[h], __shfl_xor_sync(0xffffffffu, lm[h], o));
    float ls[8];
#pragma unroll
    for (int h = 0; h < 8; h++) ls[h] = 0.f;
    for (int j = start + lane; j < end; j += 32) {
        int s = g_csr[j];
        float4 aA = *(const float4*)(g_as + s * 8);
        float4 aB = *(const float4*)(g_as + s * 8 + 4);
        float e;
        e = aA.x + ad0; e = (e > 0.f) ? e : 0.2f * e; ls[0] += __expf(e - lm[0]);
        e = aA.y + ad1; e = (e > 0.f) ? e : 0.2f * e; ls[1] += __expf(e - lm[1]);
        e = aA.z + ad2; e = (e > 0.f) ? e : 0.2f * e; ls[2] += __expf(e - lm[2]);
        e = aA.w + ad3; e = (e > 0.f) ? e : 0.2f * e; ls[3] += __expf(e - lm[3]);
        e = aB.x + ad4; e = (e > 0.f) ? e : 0.2f * e; ls[4] += __expf(e - lm[4]);
        e = aB.y + ad5; e = (e > 0.f) ? e : 0.2f * e; ls[5] += __expf(e - lm[5]);
        e = aB.z + ad6; e = (e > 0.f) ? e : 0.2f * e; ls[6] += __expf(e - lm[6]);
        e = aB.w + ad7; e = (e > 0.f) ? e : 0.2f * e; ls[7] += __expf(e - lm[7]);
    }
#pragma unroll
    for (int h = 0; h < 8; h++)
        for (int o = 16; o; o >>= 1)
            ls[h] += __shfl_xor_sync(0xffffffffu, ls[h], o);
    float inv[8];
#pragma unroll
    for (int h = 0; h < 8; h++) inv[h] = 1.f / ls[h];

    float advl = (lane == 0) ? ad0 : (lane == 1) ? ad1 : (lane == 2) ? ad2 :
                 (lane == 3) ? ad3 : (lane == 4) ? ad4 : (lane == 5) ? ad5 :
                 (lane == 6) ? ad6 : ad7;
    float lml  = (lane == 0) ? lm[0] : (lane == 1) ? lm[1] : (lane == 2) ? lm[2] :
                 (lane == 3) ? lm[3] : (lane == 4) ? lm[4] : (lane == 5) ? lm[5] :
                 (lane == 6) ? lm[6] : lm[7];
    float invl = (lane == 0) ? inv[0] : (lane == 1) ? inv[1] : (lane == 2) ? inv[2] :
                 (lane == 3) ? inv[3] : (lane == 4) ? inv[4] : (lane == 5) ? inv[5] :
                 (lane == 6) ? inv[6] : inv[7];

    ull acc2[8];
#pragma unroll
    for (int h = 0; h < 8; h++) acc2[h] = 0ULL;
    for (int j = start; j < end; j++) {
        int s = g_csr[j];
        float alv = 0.f;
        if (lane < 8) {
            float a = g_as[s * 8 + lane];
            float e = a + advl;
            e = (e > 0.f) ? e : 0.2f * e;
            alv = __expf(e - lml) * invl;
        }
        ull v = *(const ull*)(g_h0 + (size_t)s * 64 + lane * 2);
#pragma unroll
        for (int h = 0; h < 8; h++) {
            float a = __shfl_sync(0xffffffffu, alv, h);
            fma2(acc2[h], pk2(a, a), v);
        }
    }
#pragma unroll
    for (int h = 0; h < 8; h++)
        *(ull*)(g_pre + (size_t)gw * 512 + h * 64 + lane * 2) = acc2[h];
}

// ---------------- fused: out = relu(relu(pre (x)_h Wg_h + bg) @ Wh + bh) ----
__global__ void k_fused(const float* __restrict__ Wg,
                        const float* __restrict__ bg,
                        const float* __restrict__ Wh,
                        const float* __restrict__ bh, int n) {
    __shared__ float PT[64][68];   // P_h: [k][row], later T_h: [c][row]
    __shared__ float Wgb[64][68];  // Wg_h: [k][c]
    __shared__ float Whb[64][68];  // Wh_h: [c][c2]
    int row0 = blockIdx.x * 64;
    int t = threadIdx.x;  // 128
    int tx = t & 15, ty = t >> 4;
    ull acc[4][4];
#pragma unroll
    for (int i = 0; i < 4; i++)
#pragma unroll
        for (int j = 0; j < 4; j++) acc[i][j] = 0ULL;

    for (int h = 0; h < 8; h++) {
        __syncthreads();
        for (int idx = t; idx < 4096; idx += 128) {
            int r = idx >> 6, k = idx & 63;
            int gr = row0 + r;
            PT[k][r] = (gr < n) ? g_pre[(size_t)gr * 512 + h * 64 + k] : 0.f;
        }
        for (int idx = t; idx < 4096; idx += 128) {
            int k = idx >> 6, c = idx & 63;
            Wgb[k][c] = Wg[k * 512 + h * 64 + c];
            Whb[k][c] = Wh[(h * 64 + k) * 64 + c];
        }
        __syncthreads();
        ull t4[4][4];
#pragma unroll
        for (int i = 0; i < 4; i++)
#pragma unroll
            for (int j = 0; j < 4; j++) t4[i][j] = 0ULL;
#pragma unroll 4
        for (int k = 0; k < 64; k++) {
            const ull* ap = (const ull*)&PT[k][ty * 8];
            ull a0 = ap[0], a1 = ap[1], a2 = ap[2], a3 = ap[3];
            float4 bv = *(const float4*)&Wgb[k][tx * 4];
            ull b0 = pk2(bv.x, bv.x), b1 = pk2(bv.y, bv.y);
            ull b2 = pk2(bv.z, bv.z), b3 = pk2(bv.w, bv.w);
            fma2(t4[0][0], a0, b0); fma2(t4[0][1], a0, b1);
            fma2(t4[0][2], a0, b2); fma2(t4[0][3], a0, b3);
            fma2(t4[1][0], a1, b0); fma2(t4[1][1], a1, b1);
            fma2(t4[1][2], a1, b2); fma2(t4[1][3], a1, b3);
            fma2(t4[2][0], a2, b0); fma2(t4[2][1], a2, b1);
            fma2(t4[2][2], a2, b2); fma2(t4[2][3], a2, b3);
            fma2(t4[3][0], a3, b0); fma2(t4[3][1], a3, b1);
            fma2(t4[3][2], a3, b2); fma2(t4[3][3], a3, b3);
        }
        __syncthreads();  // PT reads done before T overwrite
#pragma unroll
        for (int j = 0; j < 4; j++) {
            float bgv = bg[h * 64 + tx * 4 + j];
#pragma unroll
            for (int i = 0; i < 4; i++) {
                float e0, e1;
                upk2(t4[i][j], e0, e1);
                PT[tx * 4 + j][ty * 8 + 2 * i]     = fmaxf(e0 + bgv, 0.f);
                PT[tx * 4 + j][ty * 8 + 2 * i + 1] = fmaxf(e1 + bgv, 0.f);
            }
        }
        __syncthreads();
#pragma unroll 4
        for (int k = 0; k < 64; k++) {
            const ull* ap = (const ull*)&PT[k][ty * 8];
            ull a0 = ap[0], a1 = ap[1], a2 = ap[2], a3 = ap[3];
            float4 bv = *(const float4*)&Whb[k][tx * 4];
            ull b0 = pk2(bv.x, bv.x), b1 = pk2(bv.y, bv.y);
            ull b2 = pk2(bv.z, bv.z), b3 = pk2(bv.w, bv.w);
            fma2(acc[0][0], a0, b0); fma2(acc[0][1], a0, b1);
            fma2(acc[0][2], a0, b2); fma2(acc[0][3], a0, b3);
            fma2(acc[1][0], a1, b0); fma2(acc[1][1], a1, b1);
            fma2(acc[1][2], a1, b2); fma2(acc[1][3], a1, b3);
            fma2(acc[2][0], a2, b0); fma2(acc[2][1], a2, b1);
            fma2(acc[2][2], a2, b2); fma2(acc[2][3], a2, b3);
            fma2(acc[3][0], a3, b0); fma2(acc[3][1], a3, b1);
            fma2(acc[3][2], a3, b2); fma2(acc[3][3], a3, b3);
        }
    }
    float4 bhv = *(const float4*)&bh[tx * 4];
#pragma unroll
    for (int i = 0; i < 4; i++) {
        float x0[4], x1[4];
#pragma unroll
        for (int j = 0; j < 4; j++) upk2(acc[i][j], x0[j], x1[j]);
        int gr0 = row0 + ty * 8 + 2 * i;
        int gr1 = gr0 + 1;
        if (gr0 < n) {
            float4 v;
            v.x = fmaxf(x0[0] + bhv.x, 0.f);
            v.y = fmaxf(x0[1] + bhv.y, 0.f);
            v.z = fmaxf(x0[2] + bhv.z, 0.f);
            v.w = fmaxf(x0[3] + bhv.w, 0.f);
            *(float4*)(g_outf + gr0 * 64 + tx * 4) = v;
        }
        if (gr1 < n) {
            float4 v;
            v.x = fmaxf(x1[0] + bhv.x, 0.f);
            v.y = fmaxf(x1[1] + bhv.y, 0.f);
            v.z = fmaxf(x1[2] + bhv.z, 0.f);
            v.w = fmaxf(x1[3] + bhv.w, 0.f);
            *(float4*)(g_outf + gr1 * 64 + tx * 4) = v;
        }
    }
}

// ---------------- Set2Set: all 3 iterations + final MLP in ONE kernel -------
__global__ void k_s2s(const float* __restrict__ W_ih,
                      const float* __restrict__ W_hh,
                      const float* __restrict__ b_ih,
                      const float* __restrict__ b_hh,
                      const float* __restrict__ W1, const float* __restrict__ b1,
                      const float* __restrict__ W2, const float* __restrict__ b2,
                      float* __restrict__ y) {
    int b = blockIdx.x, t = threadIdx.x;  // 256 threads
    int lane = t & 31, wid = t >> 5;
    __shared__ float qstar[128], hh[64], cc[64], gg[256], q[64], sb[8];
    __shared__ float rr[4][64];
    if (t < 128) qstar[t] = 0.f;
    if (t < 64) { hh[t] = 0.f; cc[t] = 0.f; }
    __syncthreads();
    int s0 = g_seg[b], s1 = g_seg[b + 1];

    for (int it = 0; it < 3; it++) {
        {
            float acc = b_ih[t] + b_hh[t];
            const float* wr = W_ih + t * 128;
#pragma unroll 8
            for (int k = 0; k < 128; k++) acc += qstar[k] * wr[k];
            const float* wr2 = W_hh + t * 64;
#pragma unroll 8
            for (int k = 0; k < 64; k++) acc += hh[k] * wr2[k];
            gg[t] = acc;
        }
        __syncthreads();
        if (t < 64) {
            float ig = 1.f / (1.f + __expf(-gg[t]));
            float fg = 1.f / (1.f + __expf(-gg[64 + t]));
            float gv = tanhf(gg[128 + t]);
            float og = 1.f / (1.f + __expf(-gg[192 + t]));
            float cn = fg * cc[t] + ig * gv;
            float hn = og * tanhf(cn);
            cc[t] = cn;
            hh[t] = hn;
            q[t] = hn;
        }
        __syncthreads();
        float mx = -1e30f;
        for (int i = s0 + t; i < s1; i += 256) {
            const float* row = g_outf + i * 64;
            float d = 0.f;
#pragma unroll
            for (int c = 0; c < 64; c += 4) {
                float4 v = *(const float4*)(row + c);
                d += v.x * q[c] + v.y * q[c + 1] + v.z * q[c + 2] + v.w * q[c + 3];
            }
            g_e2[i] = d;
            mx = fmaxf(mx, d);
        }
        for (int o = 16; o; o >>= 1)
            mx = fmaxf(mx, __shfl_xor_sync(0xffffffffu, mx, o));
        if (lane == 0) sb[wid] = mx;
        __syncthreads();
        mx = fmaxf(fmaxf(fmaxf(sb[0], sb[1]), fmaxf(sb[2], sb[3])),
                   fmaxf(fmaxf(sb[4], sb[5]), fmaxf(sb[6], sb[7])));
        __syncthreads();
        float sm = 0.f;
        for (int i = s0 + t; i < s1; i += 256) {
            float w = __expf(g_e2[i] - mx);
            g_e2[i] = w;
            sm += w;
        }
        for (int o = 16; o; o >>= 1) sm += __shfl_xor_sync(0xffffffffu, sm, o);
        if (lane == 0) sb[wid] = sm;
        __syncthreads();
        sm = sb[0] + sb[1] + sb[2] + sb[3] + sb[4] + sb[5] + sb[6] + sb[7];
        float inv = (sm > 0.f) ? 1.f / sm : 0.f;
        __syncthreads();
        {
            int grp = t >> 6, ch = t & 63;
            float r0 = 0.f, r1 = 0.f, r2 = 0.f, r3 = 0.f;
            int i = s0 + grp;
            for (; i + 12 < s1; i += 16) {
                r0 += g_e2[i]      * g_outf[i * 64 + ch];
                r1 += g_e2[i + 4]  * g_outf[(i + 4) * 64 + ch];
                r2 += g_e2[i + 8]  * g_outf[(i + 8) * 64 + ch];
                r3 += g_e2[i + 12] * g_outf[(i + 12) * 64 + ch];
            }
            for (; i < s1; i += 4) r0 += g_e2[i] * g_outf[i * 64 + ch];
            rr[grp][ch] = (r0 + r1) + (r2 + r3);
        }
        __syncthreads();
        if (t < 64) {
            float rt = (rr[0][t] + rr[1][t] + rr[2][t] + rr[3][t]) * inv;
            qstar[t] = q[t];
            qstar[64 + t] = rt;
        }
        __syncthreads();
    }
    if (t < 64) {
        float a = b1[t];
#pragma unroll 8
        for (int k = 0; k < 128; k++) a += qstar[k] * W1[k * 64 + t];
        float z = fmaxf(a, 0.f) * W2[t];
        for (int o = 16; o; o >>= 1) z += __shfl_xor_sync(0xffffffffu, z, o);
        if (lane == 0) sb[wid] = z;
    }
    __syncthreads();
    if (t == 0) y[b] = sb[0] + sb[1] + b2[0];
}

// ---------------- launcher ---------------------------------------------------
extern "C" void kernel_launch(void* const* d_in, const int* in_sizes, int n_in,
                              void* d_out, int out_size) {
    const float* x      = (const float*)d_in[0];
    const void*  edge   = d_in[1];
    const void*  batch  = d_in[2];
    const float* W0     = (const float*)d_in[3];
    const float* b0     = (const float*)d_in[4];
    const float* Wg     = (const float*)d_in[5];
    const float* att_s  = (const float*)d_in[6];
    const float* att_d  = (const float*)d_in[7];
    const float* bg     = (const float*)d_in[8];
    const float* Wh     = (const float*)d_in[9];
    const float* bh     = (const float*)d_in[10];
    const float* W_ih   = (const float*)d_in[11];
    const float* W_hh   = (const float*)d_in[12];
    const float* b_ih   = (const float*)d_in[13];
    const float* b_hh   = (const float*)d_in[14];
    const float* W1     = (const float*)d_in[15];
    const float* b1     = (const float*)d_in[16];
    const float* W2     = (const float*)d_in[17];
    const float* b2     = (const float*)d_in[18];
    float* y = (float*)d_out;

    int n = in_sizes[0] / 25;
    int E = in_sizes[1] / 2;

    k_csrbuild<<<NBLK, 1024>>>(edge, batch, Wg, att_s, att_d, E, n);
    k_h0attn<<<(n + 15) / 16, 256>>>(x, W0, b0, n);
    k_agg<<<(n + 7) / 8, 256>>>(n);
    k_fused<<<(n + 63) / 64, 128>>>(Wg, bg, Wh, bh, n);
    k_s2s<<<BB, 256>>>(W_ih, W_hh, b_ih, b_hh, W1, b1, W2, b2, y);
}